// round 1
// baseline (speedup 1.0000x reference)
#include <cuda_runtime.h>
#include <math.h>

#define BB 2
#define LL 2048
#define DD 512
#define VV 32000
#define NLAYER 4
#define PP 8
#define TOK (BB*LL)           // 4096 tokens
#define NCH 16                // scan chunks along L
#define CHL (LL/NCH)          // 128

// ---------------- scratch (device globals: no allocation allowed) -----------
__device__ float g_h [TOK*DD];
__device__ float g_hn[TOK*DD];
__device__ float g_val[TOK*DD];
__device__ float g_sn[TOK*DD];
__device__ float g_coef[TOK];
__device__ float g_csum[BB*NCH*DD];

// ---------------- embedding gather ------------------------------------------
__global__ void k_embed(const int* __restrict__ tok, const float* __restrict__ emb) {
    int t = blockIdx.x;
    int tk = tok[t];
    const float4* src = (const float4*)(emb + (size_t)tk * DD);
    float4* dst = (float4*)(g_h + (size_t)t * DD);
    dst[threadIdx.x] = src[threadIdx.x];   // 128 threads x float4 = 512 floats
}

// ---------------- LayerNorm (one block per token, 256 threads) --------------
__global__ void k_ln(const float* __restrict__ x, const float* __restrict__ gs,
                     const float* __restrict__ gb, float* __restrict__ y) {
    int t = blockIdx.x;
    int tid = threadIdx.x;
    __shared__ float red[8];

    const float* xr = x + (size_t)t * DD;
    float a = xr[tid];
    float b = xr[tid + 256];

    // mean
    float s = a + b;
    #pragma unroll
    for (int o = 16; o; o >>= 1) s += __shfl_xor_sync(~0u, s, o);
    if ((tid & 31) == 0) red[tid >> 5] = s;
    __syncthreads();
    if (tid == 0) { float r = 0; for (int i = 0; i < 8; i++) r += red[i]; red[0] = r * (1.0f / DD); }
    __syncthreads();
    float mean = red[0];
    __syncthreads();

    // var
    float d0 = a - mean, d1 = b - mean;
    float s2 = d0 * d0 + d1 * d1;
    #pragma unroll
    for (int o = 16; o; o >>= 1) s2 += __shfl_xor_sync(~0u, s2, o);
    if ((tid & 31) == 0) red[tid >> 5] = s2;
    __syncthreads();
    if (tid == 0) { float r = 0; for (int i = 0; i < 8; i++) r += red[i]; red[0] = rsqrtf(r * (1.0f / DD) + 1e-5f); }
    __syncthreads();
    float rstd = red[0];

    float* yr = y + (size_t)t * DD;
    yr[tid]       = d0 * rstd * gs[tid]       + gb[tid];
    yr[tid + 256] = d1 * rstd * gs[tid + 256] + gb[tid + 256];
}

// ---------------- coef = sum_p amp_p * (cos(phase_p) + sin(phase_p)) --------
// one block per token, 8 warps (one per p). W matrices are [D, P] row-major.
__global__ void k_coef(const float* __restrict__ hn,
                       const float* __restrict__ pW, const float* __restrict__ pb,
                       const float* __restrict__ aW, const float* __restrict__ ab) {
    int t = blockIdx.x;
    int tid = threadIdx.x;
    __shared__ float sx[DD];
    __shared__ float terms[PP];

    const float* xr = hn + (size_t)t * DD;
    sx[tid] = xr[tid];
    sx[tid + 256] = xr[tid + 256];
    __syncthreads();

    int w = tid >> 5, lane = tid & 31;    // warp w handles output p=w
    float dp = 0.f, da = 0.f;
    #pragma unroll 4
    for (int d = lane; d < DD; d += 32) {
        float xv = sx[d];
        dp += xv * pW[d * PP + w];
        da += xv * aW[d * PP + w];
    }
    #pragma unroll
    for (int o = 16; o; o >>= 1) {
        dp += __shfl_xor_sync(~0u, dp, o);
        da += __shfl_xor_sync(~0u, da, o);
    }
    if (lane == 0) {
        float ph = tanhf(dp + pb[w]) * 3.14159265358979323846f;
        float av = da + ab[w];
        float sp = (av > 20.f) ? av : log1pf(expf(av));
        float amp = sp + 0.1f;
        float sc, cc;
        sincosf(ph, &sc, &cc);
        terms[w] = amp * (cc + sc);
    }
    __syncthreads();
    if (tid == 0) {
        float c = 0.f;
        #pragma unroll
        for (int i = 0; i < PP; i++) c += terms[i];
        g_coef[t] = c;
    }
}

// ---------------- generic SGEMM: C = A[M,K] @ W[K,N], flexible epilogue -----
// 128x128 tile, Kstep 8, 256 threads, 8x8 micro-tile. M,N,K multiples of 128/8.
// epilogue: v = acc + bias[n]; if(rowscale) v *= rowscale[m];
//           if(add0) v += add0[m*N+n]; if(add1) v += add1[m*N+n];
__global__ void __launch_bounds__(256)
k_gemm(const float* __restrict__ A, const float* __restrict__ Wm,
       const float* __restrict__ bias,
       const float* __restrict__ add0, const float* __restrict__ add1,
       const float* __restrict__ rowscale,
       float* __restrict__ C, int M, int N, int K) {
    __shared__ float As[8][128];
    __shared__ float Bs[8][128];

    int tid = threadIdx.x;
    int m0 = blockIdx.y * 128, n0 = blockIdx.x * 128;

    int arow = tid >> 1, akq = (tid & 1) * 4;          // A loader: 2 thr/row
    int brow = tid >> 5, bcol = (tid & 31) * 4;        // B loader: 32 thr/row

    const float* Ap = A + (size_t)(m0 + arow) * K + akq;
    const float* Bp = Wm + (size_t)brow * N + n0 + bcol;

    float acc[8][8];
    #pragma unroll
    for (int i = 0; i < 8; i++)
        #pragma unroll
        for (int j = 0; j < 8; j++) acc[i][j] = 0.f;

    int ty = (tid >> 4) * 8, tx = (tid & 15) * 8;

    for (int k0 = 0; k0 < K; k0 += 8) {
        float4 av = *(const float4*)(Ap + k0);
        float4 bv = *(const float4*)(Bp + (size_t)k0 * N);
        As[akq + 0][arow] = av.x;
        As[akq + 1][arow] = av.y;
        As[akq + 2][arow] = av.z;
        As[akq + 3][arow] = av.w;
        *(float4*)&Bs[brow][bcol] = bv;
        __syncthreads();

        #pragma unroll
        for (int k = 0; k < 8; k++) {
            float4 a0 = *(const float4*)&As[k][ty];
            float4 a1 = *(const float4*)&As[k][ty + 4];
            float4 b0 = *(const float4*)&Bs[k][tx];
            float4 b1 = *(const float4*)&Bs[k][tx + 4];
            float ar[8] = {a0.x, a0.y, a0.z, a0.w, a1.x, a1.y, a1.z, a1.w};
            float br[8] = {b0.x, b0.y, b0.z, b0.w, b1.x, b1.y, b1.z, b1.w};
            #pragma unroll
            for (int i = 0; i < 8; i++)
                #pragma unroll
                for (int j = 0; j < 8; j++)
                    acc[i][j] = fmaf(ar[i], br[j], acc[i][j]);
        }
        __syncthreads();
    }

    #pragma unroll
    for (int i = 0; i < 8; i++) {
        int m = m0 + ty + i;
        float rs = rowscale ? rowscale[m] : 1.f;
        #pragma unroll
        for (int j = 0; j < 8; j++) {
            int n = n0 + tx + j;
            size_t idx = (size_t)m * N + n;
            float v = acc[i][j] + bias[n];
            if (rowscale) v *= rs;
            if (add0) v += add0[idx];
            if (add1) v += add1[idx];
            C[idx] = v;
        }
    }
}

// ---------------- chunked cumsum over L (per batch, per channel) ------------
__global__ void k_chunksum() {
    int d = blockIdx.x * 128 + threadIdx.x;
    int ch = blockIdx.y, b = blockIdx.z;
    size_t base = ((size_t)(b * LL + ch * CHL)) * DD + d;
    float s = 0.f;
    #pragma unroll 8
    for (int l = 0; l < CHL; l++) s += g_val[base + (size_t)l * DD];
    g_csum[(b * NCH + ch) * DD + d] = s;
}

__global__ void k_chunkpfx() {   // 1 block, BB*DD = 1024 threads
    int idx = threadIdx.x;
    int b = idx >> 9, d = idx & 511;
    float acc = 0.f;
    #pragma unroll
    for (int ch = 0; ch < NCH; ch++) {
        size_t i = (size_t)(b * NCH + ch) * DD + d;
        float t = g_csum[i];
        g_csum[i] = acc;
        acc += t;
    }
}

__global__ void k_scan() {       // in-place: g_val <- cumsum(g_val) / sqrt(L)
    int d = blockIdx.x * 128 + threadIdx.x;
    int ch = blockIdx.y, b = blockIdx.z;
    float acc = g_csum[(b * NCH + ch) * DD + d];
    size_t base = ((size_t)(b * LL + ch * CHL)) * DD + d;
    const float inv = 0.0220970869120796089f;  // 1/sqrt(2048)
    #pragma unroll 8
    for (int l = 0; l < CHL; l++) {
        size_t i = base + (size_t)l * DD;
        acc += g_val[i];
        g_val[i] = acc * inv;
    }
}

// ---------------- launch ----------------------------------------------------
extern "C" void kernel_launch(void* const* d_in, const int* in_sizes, int n_in,
                              void* d_out, int out_size) {
    const int*   tokens        = (const int*)  d_in[0];
    const float* embed         = (const float*)d_in[1];
    const float* ln_scale      = (const float*)d_in[2];
    const float* ln_bias       = (const float*)d_in[3];
    const float* phase_W       = (const float*)d_in[4];
    const float* phase_b       = (const float*)d_in[5];
    const float* amp_W         = (const float*)d_in[6];
    const float* amp_b         = (const float*)d_in[7];
    const float* value_W       = (const float*)d_in[8];
    const float* value_b       = (const float*)d_in[9];
    const float* out_ln_scale  = (const float*)d_in[10];
    const float* out_ln_bias   = (const float*)d_in[11];
    const float* out_W         = (const float*)d_in[12];
    const float* out_b         = (const float*)d_in[13];
    const float* normout_scale = (const float*)d_in[14];
    const float* normout_bias  = (const float*)d_in[15];
    const float* head_W        = (const float*)d_in[16];
    const float* head_b        = (const float*)d_in[17];
    float* out = (float*)d_out;

    float *h, *hn, *val, *sn, *coef;
    cudaGetSymbolAddress((void**)&h,    g_h);
    cudaGetSymbolAddress((void**)&hn,   g_hn);
    cudaGetSymbolAddress((void**)&val,  g_val);
    cudaGetSymbolAddress((void**)&sn,   g_sn);
    cudaGetSymbolAddress((void**)&coef, g_coef);

    k_embed<<<TOK, 128>>>(tokens, embed);

    dim3 scanGrid(DD / 128, NCH, BB);
    dim3 gemmSmall(DD / 128, TOK / 128);   // (4, 32)

    for (int i = 0; i < NLAYER; i++) {
        // hn = LN(h)
        k_ln<<<TOK, 256>>>(h, ln_scale + i * DD, ln_bias + i * DD, hn);
        // coef[t] = sum_p amp*(cos+sin)
        k_coef<<<TOK, 256>>>(hn, phase_W + (size_t)i * DD * PP, phase_b + i * PP,
                             amp_W + (size_t)i * DD * PP, amp_b + i * PP);
        // val = (hn @ vW + vb) * coef[t]
        k_gemm<<<gemmSmall, 256>>>(hn, value_W + (size_t)i * DD * DD, value_b + i * DD,
                                   nullptr, nullptr, coef, val, TOK, DD, DD);
        // val = cumsum_L(val) / sqrt(L)
        k_chunksum<<<scanGrid, 128>>>();
        k_chunkpfx<<<1, BB * DD>>>();
        k_scan<<<scanGrid, 128>>>();
        // sn = LN(val)
        k_ln<<<TOK, 256>>>(val, out_ln_scale + i * DD, out_ln_bias + i * DD, sn);
        // h = h + hn + sn @ oW + ob
        k_gemm<<<gemmSmall, 256>>>(sn, out_W + (size_t)i * DD * DD, out_b + i * DD,
                                   h, hn, nullptr, h, TOK, DD, DD);
    }

    // final: out = LN(h) @ head_W + head_b
    k_ln<<<TOK, 256>>>(h, normout_scale, normout_bias, hn);
    k_gemm<<<dim3(VV / 128, TOK / 128), 256>>>(hn, head_W, head_b,
                                               nullptr, nullptr, nullptr,
                                               out, TOK, VV, DD);
}

// round 3
// speedup vs baseline: 1.9367x; 1.9367x over previous
#include <cuda_runtime.h>
#include <cuda_bf16.h>
#include <math.h>
#include <stdint.h>

#define BB 2
#define LL 2048
#define DD 512
#define VV 32000
#define NLAYER 4
#define PP 8
#define TOK (BB*LL)           // 4096 tokens
#define NCH 16                // scan chunks along L
#define CHL (LL/NCH)          // 128

// ---- head mma.sync GEMM geometry ----
#define HTM 128               // block tile M
#define HTN 128               // block tile N
#define HKC 32                // K per pipeline chunk (bf16)
#define NKC (DD/HKC)          // 16
#define HNT (VV/HTN)          // 250
#define HMT (TOK/HTM)         // 32
#define BLKB (128*HKC*2)      // 8192 bytes per (tile,kchunk) operand block
#define PADROW 40             // bf16 per padded smem row (32 data + 8 pad)
#define MATB (128*PADROW*2)   // 10240 bytes per padded matrix in smem
#define STG (4*MATB)          // 40960 per stage (Ah, Al, Wh, Wl)
#define SMEM_DYN (2*STG)      // 81920

// ---------------- scratch (device globals: no allocation allowed) -----------
__device__ float g_h [TOK*DD];
__device__ float g_hn[TOK*DD];
__device__ float g_val[TOK*DD];
__device__ float g_sn[TOK*DD];
__device__ float g_coef[TOK];
__device__ float g_csum[BB*NCH*DD];
// bf16 split operands, tile-chunked layout
__device__ __align__(16) unsigned char g_Whi[(size_t)VV*DD*2];
__device__ __align__(16) unsigned char g_Wlo[(size_t)VV*DD*2];
__device__ __align__(16) unsigned char g_Ahi[(size_t)TOK*DD*2];
__device__ __align__(16) unsigned char g_Alo[(size_t)TOK*DD*2];

// ---------------- helpers ----------------------------------------------------
__device__ __forceinline__ uint32_t smem_u32(const void* p) {
    uint32_t a;
    asm("{ .reg .u64 t; cvta.to.shared.u64 t, %1; cvt.u32.u64 %0, t; }"
        : "=r"(a) : "l"(p));
    return a;
}

__device__ __forceinline__ void cp16(uint32_t dst, const void* src) {
    asm volatile("cp.async.cg.shared.global [%0], [%1], 16;"
                 :: "r"(dst), "l"(src) : "memory");
}

#define MMA_BF16(d, a, b) \
    asm volatile("mma.sync.aligned.m16n8k16.row.col.f32.bf16.bf16.f32 " \
        "{%0,%1,%2,%3},{%4,%5,%6,%7},{%8,%9},{%0,%1,%2,%3};" \
        : "+f"((d)[0]), "+f"((d)[1]), "+f"((d)[2]), "+f"((d)[3]) \
        : "r"((a)[0]), "r"((a)[1]), "r"((a)[2]), "r"((a)[3]), \
          "r"((b)[0]), "r"((b)[1]))

__device__ __forceinline__ uint32_t ldb(const __nv_bfloat16* base, int r, int c) {
    return *(const uint32_t*)(base + r * PADROW + c);
}

// ---------------- embedding gather ------------------------------------------
__global__ void k_embed(const int* __restrict__ tok, const float* __restrict__ emb) {
    int t = blockIdx.x;
    int tk = tok[t];
    const float4* src = (const float4*)(emb + (size_t)tk * DD);
    float4* dst = (float4*)(g_h + (size_t)t * DD);
    dst[threadIdx.x] = src[threadIdx.x];
}

// ---------------- LayerNorm --------------------------------------------------
__global__ void k_ln(const float* __restrict__ x, const float* __restrict__ gs,
                     const float* __restrict__ gb, float* __restrict__ y) {
    int t = blockIdx.x;
    int tid = threadIdx.x;
    __shared__ float red[8];

    const float* xr = x + (size_t)t * DD;
    float a = xr[tid];
    float b = xr[tid + 256];

    float s = a + b;
    #pragma unroll
    for (int o = 16; o; o >>= 1) s += __shfl_xor_sync(~0u, s, o);
    if ((tid & 31) == 0) red[tid >> 5] = s;
    __syncthreads();
    if (tid == 0) { float r = 0; for (int i = 0; i < 8; i++) r += red[i]; red[0] = r * (1.0f / DD); }
    __syncthreads();
    float mean = red[0];
    __syncthreads();

    float d0 = a - mean, d1 = b - mean;
    float s2 = d0 * d0 + d1 * d1;
    #pragma unroll
    for (int o = 16; o; o >>= 1) s2 += __shfl_xor_sync(~0u, s2, o);
    if ((tid & 31) == 0) red[tid >> 5] = s2;
    __syncthreads();
    if (tid == 0) { float r = 0; for (int i = 0; i < 8; i++) r += red[i]; red[0] = rsqrtf(r * (1.0f / DD) + 1e-5f); }
    __syncthreads();
    float rstd = red[0];

    float* yr = y + (size_t)t * DD;
    yr[tid]       = d0 * rstd * gs[tid]       + gb[tid];
    yr[tid + 256] = d1 * rstd * gs[tid + 256] + gb[tid + 256];
}

// ---------------- coef = sum_p amp_p * (cos+sin)(phase_p) -------------------
__global__ void k_coef(const float* __restrict__ hn,
                       const float* __restrict__ pW, const float* __restrict__ pb,
                       const float* __restrict__ aW, const float* __restrict__ ab) {
    int t = blockIdx.x;
    int tid = threadIdx.x;
    __shared__ float sx[DD];
    __shared__ float terms[PP];

    const float* xr = hn + (size_t)t * DD;
    sx[tid] = xr[tid];
    sx[tid + 256] = xr[tid + 256];
    __syncthreads();

    int w = tid >> 5, lane = tid & 31;
    float dp = 0.f, da = 0.f;
    #pragma unroll 4
    for (int d = lane; d < DD; d += 32) {
        float xv = sx[d];
        dp += xv * pW[d * PP + w];
        da += xv * aW[d * PP + w];
    }
    #pragma unroll
    for (int o = 16; o; o >>= 1) {
        dp += __shfl_xor_sync(~0u, dp, o);
        da += __shfl_xor_sync(~0u, da, o);
    }
    if (lane == 0) {
        float ph = tanhf(dp + pb[w]) * 3.14159265358979323846f;
        float av = da + ab[w];
        float sp = (av > 20.f) ? av : log1pf(expf(av));
        float amp = sp + 0.1f;
        float sc, cc;
        sincosf(ph, &sc, &cc);
        terms[w] = amp * (cc + sc);
    }
    __syncthreads();
    if (tid == 0) {
        float c = 0.f;
        #pragma unroll
        for (int i = 0; i < PP; i++) c += terms[i];
        g_coef[t] = c;
    }
}

// ---------------- fp32 SGEMM (layer GEMMs) ----------------------------------
__global__ void __launch_bounds__(256)
k_gemm(const float* __restrict__ A, const float* __restrict__ Wm,
       const float* __restrict__ bias,
       const float* __restrict__ add0, const float* __restrict__ add1,
       const float* __restrict__ rowscale,
       float* __restrict__ C, int M, int N, int K) {
    __shared__ float As[8][128];
    __shared__ float Bs[8][128];

    int tid = threadIdx.x;
    int m0 = blockIdx.y * 128, n0 = blockIdx.x * 128;

    int arow = tid >> 1, akq = (tid & 1) * 4;
    int brow = tid >> 5, bcol = (tid & 31) * 4;

    const float* Ap = A + (size_t)(m0 + arow) * K + akq;
    const float* Bp = Wm + (size_t)brow * N + n0 + bcol;

    float acc[8][8];
    #pragma unroll
    for (int i = 0; i < 8; i++)
        #pragma unroll
        for (int j = 0; j < 8; j++) acc[i][j] = 0.f;

    int ty = (tid >> 4) * 8, tx = (tid & 15) * 8;

    for (int k0 = 0; k0 < K; k0 += 8) {
        float4 av = *(const float4*)(Ap + k0);
        float4 bv = *(const float4*)(Bp + (size_t)k0 * N);
        As[akq + 0][arow] = av.x;
        As[akq + 1][arow] = av.y;
        As[akq + 2][arow] = av.z;
        As[akq + 3][arow] = av.w;
        *(float4*)&Bs[brow][bcol] = bv;
        __syncthreads();

        #pragma unroll
        for (int k = 0; k < 8; k++) {
            float4 a0 = *(const float4*)&As[k][ty];
            float4 a1 = *(const float4*)&As[k][ty + 4];
            float4 b0 = *(const float4*)&Bs[k][tx];
            float4 b1 = *(const float4*)&Bs[k][tx + 4];
            float ar[8] = {a0.x, a0.y, a0.z, a0.w, a1.x, a1.y, a1.z, a1.w};
            float br[8] = {b0.x, b0.y, b0.z, b0.w, b1.x, b1.y, b1.z, b1.w};
            #pragma unroll
            for (int i = 0; i < 8; i++)
                #pragma unroll
                for (int j = 0; j < 8; j++)
                    acc[i][j] = fmaf(ar[i], br[j], acc[i][j]);
        }
        __syncthreads();
    }

    #pragma unroll
    for (int i = 0; i < 8; i++) {
        int m = m0 + ty + i;
        float rs = rowscale ? rowscale[m] : 1.f;
        #pragma unroll
        for (int j = 0; j < 8; j++) {
            int n = n0 + tx + j;
            size_t idx = (size_t)m * N + n;
            float v = acc[i][j] + bias[n];
            if (rowscale) v *= rs;
            if (add0) v += add0[idx];
            if (add1) v += add1[idx];
            C[idx] = v;
        }
    }
}

// ---------------- chunked cumsum over L -------------------------------------
__global__ void k_chunksum() {
    int d = blockIdx.x * 128 + threadIdx.x;
    int ch = blockIdx.y, b = blockIdx.z;
    size_t base = ((size_t)(b * LL + ch * CHL)) * DD + d;
    float s = 0.f;
    #pragma unroll 8
    for (int l = 0; l < CHL; l++) s += g_val[base + (size_t)l * DD];
    g_csum[(b * NCH + ch) * DD + d] = s;
}

__global__ void k_chunkpfx() {
    int idx = threadIdx.x;
    int b = idx >> 9, d = idx & 511;
    float acc = 0.f;
    #pragma unroll
    for (int ch = 0; ch < NCH; ch++) {
        size_t i = (size_t)(b * NCH + ch) * DD + d;
        float t = g_csum[i];
        g_csum[i] = acc;
        acc += t;
    }
}

__global__ void k_scan() {
    int d = blockIdx.x * 128 + threadIdx.x;
    int ch = blockIdx.y, b = blockIdx.z;
    float acc = g_csum[(b * NCH + ch) * DD + d];
    size_t base = ((size_t)(b * LL + ch * CHL)) * DD + d;
    const float inv = 0.0220970869120796089f;  // 1/sqrt(2048)
    #pragma unroll 8
    for (int l = 0; l < CHL; l++) {
        size_t i = base + (size_t)l * DD;
        acc += g_val[i];
        g_val[i] = acc * inv;
    }
}

// ---------------- bf16 split conversions -------------------------------------
// W [K=512, VV] row-major -> per (ntile, kc): [128 n][32 k] bf16 blocks (8KB).
// Transpose staged through smem for coalescing on both sides.
__global__ void k_convW(const float* __restrict__ W) {
    __shared__ float sm[32][132];
    int ntile = blockIdx.x, kc = blockIdx.y;
    int t = threadIdx.x;

    int n = t & 127, kh = t >> 7;
    #pragma unroll
    for (int j = 0; j < 16; j++) {
        int k = kh * 16 + j;
        sm[k][n] = W[(size_t)(kc * HKC + k) * VV + ntile * HTN + n];
    }
    __syncthreads();

    int nr = t >> 1, kp = t & 1;
    __nv_bfloat16 hi[16], lo[16];
    #pragma unroll
    for (int j = 0; j < 16; j++) {
        float v = sm[kp * 16 + j][nr];
        __nv_bfloat16 h = __float2bfloat16(v);
        hi[j] = h;
        lo[j] = __float2bfloat16(v - __bfloat162float(h));
    }
    size_t blk = ((size_t)ntile * NKC + kc) * BLKB;
    uint32_t off = nr * 64 + kp * 32;
    *(uint4*)(g_Whi + blk + off)      = ((uint4*)hi)[0];
    *(uint4*)(g_Whi + blk + off + 16) = ((uint4*)hi)[1];
    *(uint4*)(g_Wlo + blk + off)      = ((uint4*)lo)[0];
    *(uint4*)(g_Wlo + blk + off + 16) = ((uint4*)lo)[1];
}

// A [TOK, DD] row-major -> per (mtile, kc): [128 m][32 k] bf16 blocks (8KB).
__global__ void k_convA(const float* __restrict__ A) {
    int mtile = blockIdx.x, kc = blockIdx.y;
    int t = threadIdx.x;
    int m = t >> 1, kp = t & 1;
    const float* src = A + (size_t)(mtile * HTM + m) * DD + kc * HKC + kp * 16;

    __nv_bfloat16 hi[16], lo[16];
    #pragma unroll
    for (int j = 0; j < 16; j += 4) {
        float4 v = *(const float4*)(src + j);
        float vv[4] = {v.x, v.y, v.z, v.w};
        #pragma unroll
        for (int q = 0; q < 4; q++) {
            __nv_bfloat16 h = __float2bfloat16(vv[q]);
            hi[j + q] = h;
            lo[j + q] = __float2bfloat16(vv[q] - __bfloat162float(h));
        }
    }
    size_t blk = ((size_t)mtile * NKC + kc) * BLKB;
    uint32_t off = m * 64 + kp * 32;
    *(uint4*)(g_Ahi + blk + off)      = ((uint4*)hi)[0];
    *(uint4*)(g_Ahi + blk + off + 16) = ((uint4*)hi)[1];
    *(uint4*)(g_Alo + blk + off)      = ((uint4*)lo)[0];
    *(uint4*)(g_Alo + blk + off + 16) = ((uint4*)lo)[1];
}

// ---------------- head GEMM: mma.sync bf16-split, 128x128 tile ---------------
__global__ void __launch_bounds__(256)
k_head(const float* __restrict__ head_b, float* __restrict__ out) {
    extern __shared__ __align__(16) unsigned char smx[];
    int tid = threadIdx.x, wid = tid >> 5, lane = tid & 31;
    int mtile = blockIdx.x, ntile = blockIdx.y;

    const unsigned char* srcs[4];
    srcs[0] = g_Ahi + (size_t)mtile * NKC * BLKB;
    srcs[1] = g_Alo + (size_t)mtile * NKC * BLKB;
    srcs[2] = g_Whi + (size_t)ntile * NKC * BLKB;
    srcs[3] = g_Wlo + (size_t)ntile * NKC * BLKB;

    uint32_t smbase = smem_u32(smx);

    // --- pipelined copies: gmem 8KB block -> padded smem matrix -------------
    auto copy_stage = [&](int s, int kc) {
        uint32_t dst0 = smbase + s * STG;
        #pragma unroll
        for (int m = 0; m < 4; m++) {
            const unsigned char* src = srcs[m] + (size_t)kc * BLKB;
            #pragma unroll
            for (int i = 0; i < 2; i++) {
                int q = i * 256 + tid;          // 512 quads of 16B per matrix
                int row = q >> 2, c = q & 3;
                cp16(dst0 + m * MATB + row * (PADROW * 2) + c * 16,
                     src + (size_t)q * 16);
            }
        }
        asm volatile("cp.async.commit_group;" ::: "memory");
    };

    float acc[4][4][4];
    #pragma unroll
    for (int i = 0; i < 4; i++)
        #pragma unroll
        for (int j = 0; j < 4; j++)
            #pragma unroll
            for (int q = 0; q < 4; q++) acc[i][j][q] = 0.f;

    int g = lane >> 2, tig = lane & 3;
    int wm = (wid >> 2) * 64, wn = (wid & 3) * 32;

    copy_stage(0, 0);
    copy_stage(1, 1);

    for (int kc = 0; kc < NKC; kc++) {
        int s = kc & 1;
        if (kc + 1 < NKC)
            asm volatile("cp.async.wait_group 1;" ::: "memory");
        else
            asm volatile("cp.async.wait_group 0;" ::: "memory");
        __syncthreads();

        const __nv_bfloat16* Ah = (const __nv_bfloat16*)(smx + s * STG);
        const __nv_bfloat16* Al = (const __nv_bfloat16*)(smx + s * STG + MATB);
        const __nv_bfloat16* Bh = (const __nv_bfloat16*)(smx + s * STG + 2 * MATB);
        const __nv_bfloat16* Bl = (const __nv_bfloat16*)(smx + s * STG + 3 * MATB);

        #pragma unroll
        for (int kk = 0; kk < 2; kk++) {
            int k0 = kk * 16;
            uint32_t ah[4][4], al[4][4], bh[4][2], bl[4][2];
            #pragma unroll
            for (int fm = 0; fm < 4; fm++) {
                int r0 = wm + fm * 16 + g;
                ah[fm][0] = ldb(Ah, r0,     k0 + tig * 2);
                ah[fm][1] = ldb(Ah, r0 + 8, k0 + tig * 2);
                ah[fm][2] = ldb(Ah, r0,     k0 + 8 + tig * 2);
                ah[fm][3] = ldb(Ah, r0 + 8, k0 + 8 + tig * 2);
                al[fm][0] = ldb(Al, r0,     k0 + tig * 2);
                al[fm][1] = ldb(Al, r0 + 8, k0 + tig * 2);
                al[fm][2] = ldb(Al, r0,     k0 + 8 + tig * 2);
                al[fm][3] = ldb(Al, r0 + 8, k0 + 8 + tig * 2);
            }
            #pragma unroll
            for (int fn = 0; fn < 4; fn++) {
                int r0 = wn + fn * 8 + g;
                bh[fn][0] = ldb(Bh, r0, k0 + tig * 2);
                bh[fn][1] = ldb(Bh, r0, k0 + 8 + tig * 2);
                bl[fn][0] = ldb(Bl, r0, k0 + tig * 2);
                bl[fn][1] = ldb(Bl, r0, k0 + 8 + tig * 2);
            }
            #pragma unroll
            for (int fm = 0; fm < 4; fm++)
                #pragma unroll
                for (int fn = 0; fn < 4; fn++) {
                    MMA_BF16(acc[fm][fn], ah[fm], bh[fn]);
                    MMA_BF16(acc[fm][fn], ah[fm], bl[fn]);
                    MMA_BF16(acc[fm][fn], al[fm], bh[fn]);
                }
        }
        __syncthreads();
        if (kc + 2 < NKC) copy_stage(s, kc + 2);
    }

    // --- epilogue -----------------------------------------------------------
    int orow0 = mtile * HTM + wm + g;
    int ocol0 = ntile * HTN + wn + tig * 2;
    #pragma unroll
    for (int fn = 0; fn < 4; fn++) {
        int c = ocol0 + fn * 8;
        float b0 = head_b[c], b1 = head_b[c + 1];
        #pragma unroll
        for (int fm = 0; fm < 4; fm++) {
            int r = orow0 + fm * 16;
            float2 v0 = {acc[fm][fn][0] + b0, acc[fm][fn][1] + b1};
            float2 v1 = {acc[fm][fn][2] + b0, acc[fm][fn][3] + b1};
            *(float2*)(out + (size_t)r * VV + c)       = v0;
            *(float2*)(out + (size_t)(r + 8) * VV + c) = v1;
        }
    }
}

// ---------------- launch ----------------------------------------------------
extern "C" void kernel_launch(void* const* d_in, const int* in_sizes, int n_in,
                              void* d_out, int out_size) {
    const int*   tokens        = (const int*)  d_in[0];
    const float* embed         = (const float*)d_in[1];
    const float* ln_scale      = (const float*)d_in[2];
    const float* ln_bias       = (const float*)d_in[3];
    const float* phase_W       = (const float*)d_in[4];
    const float* phase_b       = (const float*)d_in[5];
    const float* amp_W         = (const float*)d_in[6];
    const float* amp_b         = (const float*)d_in[7];
    const float* value_W       = (const float*)d_in[8];
    const float* value_b       = (const float*)d_in[9];
    const float* out_ln_scale  = (const float*)d_in[10];
    const float* out_ln_bias   = (const float*)d_in[11];
    const float* out_W         = (const float*)d_in[12];
    const float* out_b         = (const float*)d_in[13];
    const float* normout_scale = (const float*)d_in[14];
    const float* normout_bias  = (const float*)d_in[15];
    const float* head_W        = (const float*)d_in[16];
    const float* head_b        = (const float*)d_in[17];
    float* out = (float*)d_out;

    float *h, *hn, *val, *sn, *coef;
    cudaGetSymbolAddress((void**)&h,    g_h);
    cudaGetSymbolAddress((void**)&hn,   g_hn);
    cudaGetSymbolAddress((void**)&val,  g_val);
    cudaGetSymbolAddress((void**)&sn,   g_sn);
    cudaGetSymbolAddress((void**)&coef, g_coef);

    cudaFuncSetAttribute(k_head, cudaFuncAttributeMaxDynamicSharedMemorySize, SMEM_DYN);

    k_embed<<<TOK, 128>>>(tokens, embed);
    // W conversion depends only on inputs; overlaps with the layer stack
    k_convW<<<dim3(HNT, NKC), 256>>>(head_W);

    dim3 scanGrid(DD / 128, NCH, BB);
    dim3 gemmSmall(DD / 128, TOK / 128);

    for (int i = 0; i < NLAYER; i++) {
        k_ln<<<TOK, 256>>>(h, ln_scale + i * DD, ln_bias + i * DD, hn);
        k_coef<<<TOK, 256>>>(hn, phase_W + (size_t)i * DD * PP, phase_b + i * PP,
                             amp_W + (size_t)i * DD * PP, amp_b + i * PP);
        k_gemm<<<gemmSmall, 256>>>(hn, value_W + (size_t)i * DD * DD, value_b + i * DD,
                                   nullptr, nullptr, coef, val, TOK, DD, DD);
        k_chunksum<<<scanGrid, 128>>>();
        k_chunkpfx<<<1, BB * DD>>>();
        k_scan<<<scanGrid, 128>>>();
        k_ln<<<TOK, 256>>>(val, out_ln_scale + i * DD, out_ln_bias + i * DD, sn);
        k_gemm<<<gemmSmall, 256>>>(sn, out_W + (size_t)i * DD * DD, out_b + i * DD,
                                   h, hn, nullptr, h, TOK, DD, DD);
    }

    k_ln<<<TOK, 256>>>(h, normout_scale, normout_bias, hn);
    k_convA<<<dim3(HMT, NKC), 256>>>(hn);
    k_head<<<dim3(HMT, HNT), 256, SMEM_DYN>>>(head_b, out);
}

// round 4
// speedup vs baseline: 2.3645x; 1.2209x over previous
#include <cuda_runtime.h>
#include <cuda_bf16.h>
#include <math.h>
#include <stdint.h>

#define BB 2
#define LL 2048
#define DD 512
#define VV 32000
#define NLAYER 4
#define PP 8
#define TOK (BB*LL)           // 4096 tokens
#define NCH 16                // scan chunks along L
#define CHL (LL/NCH)          // 128

// ---- mma.sync GEMM geometry (shared by head + layer GEMMs) ----
#define HTM 128               // block tile M
#define HTN 128               // block tile N
#define HKC 32                // K per pipeline chunk (bf16)
#define NKC (DD/HKC)          // 16
#define HNT (VV/HTN)          // 250  (head)
#define LNT (DD/HTN)          // 4    (layer)
#define HMT (TOK/HTM)         // 32
#define BLKB (128*HKC*2)      // 8192 bytes per (tile,kchunk) operand block
#define PADROW 40             // bf16 per padded smem row (32 data + 8 pad)
#define MATB (128*PADROW*2)   // 10240 bytes per padded matrix in smem
#define STG (4*MATB)          // 40960 per stage (Ah, Al, Bh, Bl)
#define SMEM_DYN (2*STG)      // 81920

// ---------------- scratch (device globals: no allocation allowed) -----------
__device__ float g_h [TOK*DD];
__device__ float g_hn[TOK*DD];
__device__ float g_val[TOK*DD];
__device__ float g_sn[TOK*DD];
__device__ float g_coef[TOK];
__device__ float g_csum[BB*NCH*DD];
// bf16 split operands, tile-chunked layout
__device__ __align__(16) unsigned char g_Whi[(size_t)VV*DD*2];
__device__ __align__(16) unsigned char g_Wlo[(size_t)VV*DD*2];
__device__ __align__(16) unsigned char g_Ahi[(size_t)TOK*DD*2];
__device__ __align__(16) unsigned char g_Alo[(size_t)TOK*DD*2];
// layer weights: (layer, {value,out}, ntile, kc) blocks
__device__ __align__(16) unsigned char g_LWhi[(size_t)NLAYER*2*DD*DD*2];
__device__ __align__(16) unsigned char g_LWlo[(size_t)NLAYER*2*DD*DD*2];

// ---------------- helpers ----------------------------------------------------
__device__ __forceinline__ uint32_t smem_u32(const void* p) {
    uint32_t a;
    asm("{ .reg .u64 t; cvta.to.shared.u64 t, %1; cvt.u32.u64 %0, t; }"
        : "=r"(a) : "l"(p));
    return a;
}

__device__ __forceinline__ void cp16(uint32_t dst, const void* src) {
    asm volatile("cp.async.cg.shared.global [%0], [%1], 16;"
                 :: "r"(dst), "l"(src) : "memory");
}

#define MMA_BF16(d, a, b) \
    asm volatile("mma.sync.aligned.m16n8k16.row.col.f32.bf16.bf16.f32 " \
        "{%0,%1,%2,%3},{%4,%5,%6,%7},{%8,%9},{%0,%1,%2,%3};" \
        : "+f"((d)[0]), "+f"((d)[1]), "+f"((d)[2]), "+f"((d)[3]) \
        : "r"((a)[0]), "r"((a)[1]), "r"((a)[2]), "r"((a)[3]), \
          "r"((b)[0]), "r"((b)[1]))

__device__ __forceinline__ uint32_t ldb(const __nv_bfloat16* base, int r, int c) {
    return *(const uint32_t*)(base + r * PADROW + c);
}

// ---------------- embedding gather ------------------------------------------
__global__ void k_embed(const int* __restrict__ tok, const float* __restrict__ emb) {
    int t = blockIdx.x;
    int tk = tok[t];
    const float4* src = (const float4*)(emb + (size_t)tk * DD);
    float4* dst = (float4*)(g_h + (size_t)t * DD);
    dst[threadIdx.x] = src[threadIdx.x];
}

// ---------------- LayerNorm + fused bf16 hi/lo split output -----------------
// y (float) always written; if ohi != nullptr, also writes tile-chunked split.
__global__ void k_ln(const float* __restrict__ x, const float* __restrict__ gs,
                     const float* __restrict__ gb, float* __restrict__ y,
                     unsigned char* __restrict__ ohi, unsigned char* __restrict__ olo) {
    int t = blockIdx.x;
    int tid = threadIdx.x;
    __shared__ float red[8];

    const float* xr = x + (size_t)t * DD;
    float a = xr[tid];
    float b = xr[tid + 256];

    float s = a + b;
    #pragma unroll
    for (int o = 16; o; o >>= 1) s += __shfl_xor_sync(~0u, s, o);
    if ((tid & 31) == 0) red[tid >> 5] = s;
    __syncthreads();
    if (tid == 0) { float r = 0; for (int i = 0; i < 8; i++) r += red[i]; red[0] = r * (1.0f / DD); }
    __syncthreads();
    float mean = red[0];
    __syncthreads();

    float d0 = a - mean, d1 = b - mean;
    float s2 = d0 * d0 + d1 * d1;
    #pragma unroll
    for (int o = 16; o; o >>= 1) s2 += __shfl_xor_sync(~0u, s2, o);
    if ((tid & 31) == 0) red[tid >> 5] = s2;
    __syncthreads();
    if (tid == 0) { float r = 0; for (int i = 0; i < 8; i++) r += red[i]; red[0] = rsqrtf(r * (1.0f / DD) + 1e-5f); }
    __syncthreads();
    float rstd = red[0];

    float v0 = d0 * rstd * gs[tid]       + gb[tid];
    float v1 = d1 * rstd * gs[tid + 256] + gb[tid + 256];
    float* yr = y + (size_t)t * DD;
    yr[tid]       = v0;
    yr[tid + 256] = v1;

    if (ohi) {
        int mtile = t >> 7, mrow = t & 127;
        #pragma unroll
        for (int half = 0; half < 2; half++) {
            int d = tid + half * 256;
            float v = half ? v1 : v0;
            __nv_bfloat16 h = __float2bfloat16(v);
            __nv_bfloat16 l = __float2bfloat16(v - __bfloat162float(h));
            int kc = d >> 5, ko = d & 31;
            size_t off = ((size_t)mtile * NKC + kc) * BLKB + mrow * 64 + ko * 2;
            *(__nv_bfloat16*)(ohi + off) = h;
            *(__nv_bfloat16*)(olo + off) = l;
        }
    }
}

// ---------------- coef: 64 tokens/block, weights staged in smem -------------
__global__ void __launch_bounds__(256)
k_coef(const float* __restrict__ hn,
       const float* __restrict__ pW, const float* __restrict__ pb,
       const float* __restrict__ aW, const float* __restrict__ ab) {
    __shared__ float sW[DD][20];   // [d][p<8: phase, 8..15: amp], pad to 20
    int tid = threadIdx.x;

    for (int i = tid; i < DD * PP; i += 256) {
        int d = i >> 3, p = i & 7;
        sW[d][p]     = pW[i];
        sW[d][p + 8] = aW[i];
    }
    __syncthreads();

    int warp = tid >> 5, lane = tid & 31;
    #pragma unroll 1
    for (int tt = 0; tt < 8; tt++) {
        int t = blockIdx.x * 64 + warp * 8 + tt;
        const float* x = hn + (size_t)t * DD;
        float acc[16];
        #pragma unroll
        for (int p = 0; p < 16; p++) acc[p] = 0.f;

        #pragma unroll 4
        for (int i = 0; i < 16; i++) {
            int d = lane + i * 32;
            float xv = x[d];
            float4 w0 = *(const float4*)&sW[d][0];
            float4 w1 = *(const float4*)&sW[d][4];
            float4 w2 = *(const float4*)&sW[d][8];
            float4 w3 = *(const float4*)&sW[d][12];
            acc[0]  = fmaf(xv, w0.x, acc[0]);  acc[1]  = fmaf(xv, w0.y, acc[1]);
            acc[2]  = fmaf(xv, w0.z, acc[2]);  acc[3]  = fmaf(xv, w0.w, acc[3]);
            acc[4]  = fmaf(xv, w1.x, acc[4]);  acc[5]  = fmaf(xv, w1.y, acc[5]);
            acc[6]  = fmaf(xv, w1.z, acc[6]);  acc[7]  = fmaf(xv, w1.w, acc[7]);
            acc[8]  = fmaf(xv, w2.x, acc[8]);  acc[9]  = fmaf(xv, w2.y, acc[9]);
            acc[10] = fmaf(xv, w2.z, acc[10]); acc[11] = fmaf(xv, w2.w, acc[11]);
            acc[12] = fmaf(xv, w3.x, acc[12]); acc[13] = fmaf(xv, w3.y, acc[13]);
            acc[14] = fmaf(xv, w3.z, acc[14]); acc[15] = fmaf(xv, w3.w, acc[15]);
        }
        #pragma unroll
        for (int p = 0; p < 16; p++)
            #pragma unroll
            for (int o = 16; o; o >>= 1) acc[p] += __shfl_xor_sync(~0u, acc[p], o);

        if (lane == 0) {
            float c = 0.f;
            #pragma unroll
            for (int p = 0; p < PP; p++) {
                float ph = tanhf(acc[p] + pb[p]) * 3.14159265358979323846f;
                float av = acc[p + 8] + ab[p];
                float sp = (av > 20.f) ? av : log1pf(expf(av));
                float sc, cc;
                sincosf(ph, &sc, &cc);
                c += (sp + 0.1f) * (cc + sc);
            }
            g_coef[t] = c;
        }
    }
}

// ---------------- chunked cumsum over L -------------------------------------
__global__ void k_chunksum() {
    int d = blockIdx.x * 128 + threadIdx.x;
    int ch = blockIdx.y, b = blockIdx.z;
    size_t base = ((size_t)(b * LL + ch * CHL)) * DD + d;
    float s = 0.f;
    #pragma unroll 8
    for (int l = 0; l < CHL; l++) s += g_val[base + (size_t)l * DD];
    g_csum[(b * NCH + ch) * DD + d] = s;
}

__global__ void k_chunkpfx() {
    int idx = threadIdx.x;
    int b = idx >> 9, d = idx & 511;
    float acc = 0.f;
    #pragma unroll
    for (int ch = 0; ch < NCH; ch++) {
        size_t i = (size_t)(b * NCH + ch) * DD + d;
        float t = g_csum[i];
        g_csum[i] = acc;
        acc += t;
    }
}

__global__ void k_scan() {
    int d = blockIdx.x * 128 + threadIdx.x;
    int ch = blockIdx.y, b = blockIdx.z;
    float acc = g_csum[(b * NCH + ch) * DD + d];
    size_t base = ((size_t)(b * LL + ch * CHL)) * DD + d;
    const float inv = 0.0220970869120796089f;  // 1/sqrt(2048)
    #pragma unroll 8
    for (int l = 0; l < CHL; l++) {
        size_t i = base + (size_t)l * DD;
        acc += g_val[i];
        g_val[i] = acc * inv;
    }
}

// ---------------- bf16 split conversion: W [K, ldw] -> tile-chunked B -------
// per (ntile, kc): [128 n][32 k] bf16 blocks (8KB). Transpose via smem.
__global__ void k_convB(const float* __restrict__ W, int ldw,
                        unsigned char* __restrict__ dhi, unsigned char* __restrict__ dlo) {
    __shared__ float sm[32][132];
    int ntile = blockIdx.x, kc = blockIdx.y;
    int t = threadIdx.x;

    int n = t & 127, kh = t >> 7;
    #pragma unroll
    for (int j = 0; j < 16; j++) {
        int k = kh * 16 + j;
        sm[k][n] = W[(size_t)(kc * HKC + k) * ldw + ntile * HTN + n];
    }
    __syncthreads();

    int nr = t >> 1, kp = t & 1;
    __nv_bfloat16 hi[16], lo[16];
    #pragma unroll
    for (int j = 0; j < 16; j++) {
        float v = sm[kp * 16 + j][nr];
        __nv_bfloat16 h = __float2bfloat16(v);
        hi[j] = h;
        lo[j] = __float2bfloat16(v - __bfloat162float(h));
    }
    size_t blk = ((size_t)ntile * NKC + kc) * BLKB;
    uint32_t off = nr * 64 + kp * 32;
    *(uint4*)(dhi + blk + off)      = ((uint4*)hi)[0];
    *(uint4*)(dhi + blk + off + 16) = ((uint4*)hi)[1];
    *(uint4*)(dlo + blk + off)      = ((uint4*)lo)[0];
    *(uint4*)(dlo + blk + off + 16) = ((uint4*)lo)[1];
}

// ---------------- unified mma.sync bf16-split GEMM, 128x128 tile -------------
// C[m, 0..ldc) ; epilogue: v = acc + bias[n]; if rowscale v *= rowscale[m];
// if add0 v += add0[m*ldc+n]; if add1 v += add1[m*ldc+n].
__global__ void __launch_bounds__(256)
k_mm(const unsigned char* __restrict__ Ahi_b, const unsigned char* __restrict__ Alo_b,
     const unsigned char* __restrict__ Bhi_b, const unsigned char* __restrict__ Blo_b,
     const float* __restrict__ bias, const float* __restrict__ rowscale,
     const float* __restrict__ add0, const float* __restrict__ add1,
     float* __restrict__ C, int ldc) {
    extern __shared__ __align__(16) unsigned char smx[];
    int tid = threadIdx.x, wid = tid >> 5, lane = tid & 31;
    int mtile = blockIdx.x, ntile = blockIdx.y;

    const unsigned char* srcs[4];
    srcs[0] = Ahi_b + (size_t)mtile * NKC * BLKB;
    srcs[1] = Alo_b + (size_t)mtile * NKC * BLKB;
    srcs[2] = Bhi_b + (size_t)ntile * NKC * BLKB;
    srcs[3] = Blo_b + (size_t)ntile * NKC * BLKB;

    uint32_t smbase = smem_u32(smx);

    auto copy_stage = [&](int s, int kc) {
        uint32_t dst0 = smbase + s * STG;
        #pragma unroll
        for (int m = 0; m < 4; m++) {
            const unsigned char* src = srcs[m] + (size_t)kc * BLKB;
            #pragma unroll
            for (int i = 0; i < 2; i++) {
                int q = i * 256 + tid;          // 512 quads of 16B per matrix
                int row = q >> 2, c = q & 3;
                cp16(dst0 + m * MATB + row * (PADROW * 2) + c * 16,
                     src + (size_t)q * 16);
            }
        }
        asm volatile("cp.async.commit_group;" ::: "memory");
    };

    float acc[4][4][4];
    #pragma unroll
    for (int i = 0; i < 4; i++)
        #pragma unroll
        for (int j = 0; j < 4; j++)
            #pragma unroll
            for (int q = 0; q < 4; q++) acc[i][j][q] = 0.f;

    int g = lane >> 2, tig = lane & 3;
    int wm = (wid >> 2) * 64, wn = (wid & 3) * 32;

    copy_stage(0, 0);
    copy_stage(1, 1);

    for (int kc = 0; kc < NKC; kc++) {
        int s = kc & 1;
        if (kc + 1 < NKC)
            asm volatile("cp.async.wait_group 1;" ::: "memory");
        else
            asm volatile("cp.async.wait_group 0;" ::: "memory");
        __syncthreads();

        const __nv_bfloat16* Ah = (const __nv_bfloat16*)(smx + s * STG);
        const __nv_bfloat16* Al = (const __nv_bfloat16*)(smx + s * STG + MATB);
        const __nv_bfloat16* Bh = (const __nv_bfloat16*)(smx + s * STG + 2 * MATB);
        const __nv_bfloat16* Bl = (const __nv_bfloat16*)(smx + s * STG + 3 * MATB);

        #pragma unroll
        for (int kk = 0; kk < 2; kk++) {
            int k0 = kk * 16;
            uint32_t ah[4][4], al[4][4], bh[4][2], bl[4][2];
            #pragma unroll
            for (int fm = 0; fm < 4; fm++) {
                int r0 = wm + fm * 16 + g;
                ah[fm][0] = ldb(Ah, r0,     k0 + tig * 2);
                ah[fm][1] = ldb(Ah, r0 + 8, k0 + tig * 2);
                ah[fm][2] = ldb(Ah, r0,     k0 + 8 + tig * 2);
                ah[fm][3] = ldb(Ah, r0 + 8, k0 + 8 + tig * 2);
                al[fm][0] = ldb(Al, r0,     k0 + tig * 2);
                al[fm][1] = ldb(Al, r0 + 8, k0 + tig * 2);
                al[fm][2] = ldb(Al, r0,     k0 + 8 + tig * 2);
                al[fm][3] = ldb(Al, r0 + 8, k0 + 8 + tig * 2);
            }
            #pragma unroll
            for (int fn = 0; fn < 4; fn++) {
                int r0 = wn + fn * 8 + g;
                bh[fn][0] = ldb(Bh, r0, k0 + tig * 2);
                bh[fn][1] = ldb(Bh, r0, k0 + 8 + tig * 2);
                bl[fn][0] = ldb(Bl, r0, k0 + tig * 2);
                bl[fn][1] = ldb(Bl, r0, k0 + 8 + tig * 2);
            }
            #pragma unroll
            for (int fm = 0; fm < 4; fm++)
                #pragma unroll
                for (int fn = 0; fn < 4; fn++) {
                    MMA_BF16(acc[fm][fn], ah[fm], bh[fn]);
                    MMA_BF16(acc[fm][fn], ah[fm], bl[fn]);
                    MMA_BF16(acc[fm][fn], al[fm], bh[fn]);
                }
        }
        __syncthreads();
        if (kc + 2 < NKC) copy_stage(s, kc + 2);
    }

    // --- epilogue -----------------------------------------------------------
    int orow0 = mtile * HTM + wm + g;
    int ocol0 = ntile * HTN + wn + tig * 2;
    #pragma unroll
    for (int fn = 0; fn < 4; fn++) {
        int c = ocol0 + fn * 8;
        float b0 = bias[c], b1 = bias[c + 1];
        #pragma unroll
        for (int fm = 0; fm < 4; fm++) {
            int r = orow0 + fm * 16;
            size_t i0 = (size_t)r * ldc + c;
            size_t i1 = (size_t)(r + 8) * ldc + c;
            float v00 = acc[fm][fn][0] + b0, v01 = acc[fm][fn][1] + b1;
            float v10 = acc[fm][fn][2] + b0, v11 = acc[fm][fn][3] + b1;
            if (rowscale) {
                float r0 = rowscale[r], r1 = rowscale[r + 8];
                v00 *= r0; v01 *= r0; v10 *= r1; v11 *= r1;
            }
            if (add0) {
                float2 a0 = *(const float2*)(add0 + i0);
                float2 a1 = *(const float2*)(add0 + i1);
                v00 += a0.x; v01 += a0.y; v10 += a1.x; v11 += a1.y;
            }
            if (add1) {
                float2 a0 = *(const float2*)(add1 + i0);
                float2 a1 = *(const float2*)(add1 + i1);
                v00 += a0.x; v01 += a0.y; v10 += a1.x; v11 += a1.y;
            }
            *(float2*)(C + i0) = make_float2(v00, v01);
            *(float2*)(C + i1) = make_float2(v10, v11);
        }
    }
}

// ---------------- launch ----------------------------------------------------
extern "C" void kernel_launch(void* const* d_in, const int* in_sizes, int n_in,
                              void* d_out, int out_size) {
    const int*   tokens        = (const int*)  d_in[0];
    const float* embed         = (const float*)d_in[1];
    const float* ln_scale      = (const float*)d_in[2];
    const float* ln_bias       = (const float*)d_in[3];
    const float* phase_W       = (const float*)d_in[4];
    const float* phase_b       = (const float*)d_in[5];
    const float* amp_W         = (const float*)d_in[6];
    const float* amp_b         = (const float*)d_in[7];
    const float* value_W       = (const float*)d_in[8];
    const float* value_b       = (const float*)d_in[9];
    const float* out_ln_scale  = (const float*)d_in[10];
    const float* out_ln_bias   = (const float*)d_in[11];
    const float* out_W         = (const float*)d_in[12];
    const float* out_b         = (const float*)d_in[13];
    const float* normout_scale = (const float*)d_in[14];
    const float* normout_bias  = (const float*)d_in[15];
    const float* head_W        = (const float*)d_in[16];
    const float* head_b        = (const float*)d_in[17];
    float* out = (float*)d_out;

    float *h, *hn, *val, *sn, *coef;
    unsigned char *whi, *wlo, *ahi, *alo, *lwhi, *lwlo;
    cudaGetSymbolAddress((void**)&h,    g_h);
    cudaGetSymbolAddress((void**)&hn,   g_hn);
    cudaGetSymbolAddress((void**)&val,  g_val);
    cudaGetSymbolAddress((void**)&sn,   g_sn);
    cudaGetSymbolAddress((void**)&coef, g_coef);
    cudaGetSymbolAddress((void**)&whi,  g_Whi);
    cudaGetSymbolAddress((void**)&wlo,  g_Wlo);
    cudaGetSymbolAddress((void**)&ahi,  g_Ahi);
    cudaGetSymbolAddress((void**)&alo,  g_Alo);
    cudaGetSymbolAddress((void**)&lwhi, g_LWhi);
    cudaGetSymbolAddress((void**)&lwlo, g_LWlo);

    cudaFuncSetAttribute(k_mm, cudaFuncAttributeMaxDynamicSharedMemorySize, SMEM_DYN);

    k_embed<<<TOK, 128>>>(tokens, embed);
    // weight conversions: depend only on inputs, overlap with layer stack
    k_convB<<<dim3(HNT, NKC), 256>>>(head_W, VV, whi, wlo);
    size_t lwstep = (size_t)DD * DD * 2;   // bytes per matrix
    for (int i = 0; i < NLAYER; i++) {
        k_convB<<<dim3(LNT, NKC), 256>>>(value_W + (size_t)i * DD * DD, DD,
                                         lwhi + (2*i+0)*lwstep, lwlo + (2*i+0)*lwstep);
        k_convB<<<dim3(LNT, NKC), 256>>>(out_W + (size_t)i * DD * DD, DD,
                                         lwhi + (2*i+1)*lwstep, lwlo + (2*i+1)*lwstep);
    }

    dim3 scanGrid(DD / 128, NCH, BB);
    dim3 mmLayer(HMT, LNT);

    for (int i = 0; i < NLAYER; i++) {
        // hn = LN(h), + split operand for value GEMM
        k_ln<<<TOK, 256>>>(h, ln_scale + i * DD, ln_bias + i * DD, hn, ahi, alo);
        k_coef<<<TOK / 64, 256>>>(hn, phase_W + (size_t)i * DD * PP, phase_b + i * PP,
                                  amp_W + (size_t)i * DD * PP, amp_b + i * PP);
        // val = (hn @ vW + vb) * coef
        k_mm<<<mmLayer, 256, SMEM_DYN>>>(ahi, alo,
                                         lwhi + (2*i+0)*lwstep, lwlo + (2*i+0)*lwstep,
                                         value_b + i * DD, coef, nullptr, nullptr,
                                         val, DD);
        k_chunksum<<<scanGrid, 128>>>();
        k_chunkpfx<<<1, BB * DD>>>();
        k_scan<<<scanGrid, 128>>>();
        // sn = LN(val), + split operand for out GEMM
        k_ln<<<TOK, 256>>>(val, out_ln_scale + i * DD, out_ln_bias + i * DD, sn, ahi, alo);
        // h = h + hn + sn @ oW + ob
        k_mm<<<mmLayer, 256, SMEM_DYN>>>(ahi, alo,
                                         lwhi + (2*i+1)*lwstep, lwlo + (2*i+1)*lwstep,
                                         out_b + i * DD, nullptr, h, hn,
                                         h, DD);
    }

    // final: out = LN(h) @ head_W + head_b
    k_ln<<<TOK, 256>>>(h, normout_scale, normout_bias, hn, ahi, alo);
    k_mm<<<dim3(HMT, HNT), 256, SMEM_DYN>>>(ahi, alo, whi, wlo,
                                            head_b, nullptr, nullptr, nullptr,
                                            out, VV);
}

// round 5
// speedup vs baseline: 2.3684x; 1.0016x over previous
#include <cuda_runtime.h>
#include <cuda_bf16.h>
#include <math.h>
#include <stdint.h>

#define BB 2
#define LL 2048
#define DD 512
#define VV 32000
#define NLAYER 4
#define PP 8
#define TOK (BB*LL)           // 4096 tokens
#define NCH 16                // scan chunks along L
#define CHL (LL/NCH)          // 128

// ---- mma.sync GEMM geometry (shared by head + layer GEMMs) ----
#define HTM 128               // block tile M
#define HTN 128               // block tile N
#define HKC 32                // K per pipeline chunk (bf16)
#define NKC (DD/HKC)          // 16
#define HNT (VV/HTN)          // 250  (head)
#define LNT (DD/HTN)          // 4    (layer)
#define HMT (TOK/HTM)         // 32
#define BLKB (128*HKC*2)      // 8192 bytes per (tile,kchunk) operand block
#define PADROW 40             // bf16 per padded smem row (32 data + 8 pad)
#define PRB (PADROW*2)        // 80 bytes per padded row
#define MATB (128*PRB)        // 10240 bytes per padded matrix in smem
#define STG (4*MATB)          // 40960 per stage (Ah, Al, Bh, Bl)
#define SMEM_DYN (2*STG)      // 81920

// ---------------- scratch (device globals: no allocation allowed) -----------
__device__ float g_h [TOK*DD];
__device__ float g_hn[TOK*DD];
__device__ float g_val[TOK*DD];
__device__ float g_sn[TOK*DD];
__device__ float g_coef[TOK];
__device__ float g_csum[BB*NCH*DD];
// bf16 split operands, tile-chunked layout
__device__ __align__(16) unsigned char g_Whi[(size_t)VV*DD*2];
__device__ __align__(16) unsigned char g_Wlo[(size_t)VV*DD*2];
__device__ __align__(16) unsigned char g_Ahi[(size_t)TOK*DD*2];
__device__ __align__(16) unsigned char g_Alo[(size_t)TOK*DD*2];
// layer weights: (layer, {value,out}, ntile, kc) blocks
__device__ __align__(16) unsigned char g_LWhi[(size_t)NLAYER*2*DD*DD*2];
__device__ __align__(16) unsigned char g_LWlo[(size_t)NLAYER*2*DD*DD*2];

// ---------------- helpers ----------------------------------------------------
__device__ __forceinline__ uint32_t smem_u32(const void* p) {
    uint32_t a;
    asm("{ .reg .u64 t; cvta.to.shared.u64 t, %1; cvt.u32.u64 %0, t; }"
        : "=r"(a) : "l"(p));
    return a;
}

__device__ __forceinline__ void cp16(uint32_t dst, const void* src) {
    asm volatile("cp.async.cg.shared.global [%0], [%1], 16;"
                 :: "r"(dst), "l"(src) : "memory");
}

__device__ __forceinline__ void ldsm4(uint32_t addr, uint32_t* r) {
    asm volatile("ldmatrix.sync.aligned.m8n8.x4.shared.b16 {%0,%1,%2,%3}, [%4];"
        : "=r"(r[0]), "=r"(r[1]), "=r"(r[2]), "=r"(r[3]) : "r"(addr));
}
__device__ __forceinline__ void ldsm2(uint32_t addr, uint32_t* r) {
    asm volatile("ldmatrix.sync.aligned.m8n8.x2.shared.b16 {%0,%1}, [%2];"
        : "=r"(r[0]), "=r"(r[1]) : "r"(addr));
}

#define MMA_BF16(d, a, b) \
    asm volatile("mma.sync.aligned.m16n8k16.row.col.f32.bf16.bf16.f32 " \
        "{%0,%1,%2,%3},{%4,%5,%6,%7},{%8,%9},{%0,%1,%2,%3};" \
        : "+f"((d)[0]), "+f"((d)[1]), "+f"((d)[2]), "+f"((d)[3]) \
        : "r"((a)[0]), "r"((a)[1]), "r"((a)[2]), "r"((a)[3]), \
          "r"((b)[0]), "r"((b)[1]))

// ---------------- embedding gather ------------------------------------------
__global__ void k_embed(const int* __restrict__ tok, const float* __restrict__ emb) {
    int t = blockIdx.x;
    int tk = tok[t];
    const float4* src = (const float4*)(emb + (size_t)tk * DD);
    float4* dst = (float4*)(g_h + (size_t)t * DD);
    dst[threadIdx.x] = src[threadIdx.x];
}

// ---------------- LayerNorm + fused bf16 hi/lo split output -----------------
__global__ void k_ln(const float* __restrict__ x, const float* __restrict__ gs,
                     const float* __restrict__ gb, float* __restrict__ y,
                     unsigned char* __restrict__ ohi, unsigned char* __restrict__ olo) {
    int t = blockIdx.x;
    int tid = threadIdx.x;
    __shared__ float red[8];

    const float* xr = x + (size_t)t * DD;
    float a = xr[tid];
    float b = xr[tid + 256];

    float s = a + b;
    #pragma unroll
    for (int o = 16; o; o >>= 1) s += __shfl_xor_sync(~0u, s, o);
    if ((tid & 31) == 0) red[tid >> 5] = s;
    __syncthreads();
    if (tid == 0) { float r = 0; for (int i = 0; i < 8; i++) r += red[i]; red[0] = r * (1.0f / DD); }
    __syncthreads();
    float mean = red[0];
    __syncthreads();

    float d0 = a - mean, d1 = b - mean;
    float s2 = d0 * d0 + d1 * d1;
    #pragma unroll
    for (int o = 16; o; o >>= 1) s2 += __shfl_xor_sync(~0u, s2, o);
    if ((tid & 31) == 0) red[tid >> 5] = s2;
    __syncthreads();
    if (tid == 0) { float r = 0; for (int i = 0; i < 8; i++) r += red[i]; red[0] = rsqrtf(r * (1.0f / DD) + 1e-5f); }
    __syncthreads();
    float rstd = red[0];

    float v0 = d0 * rstd * gs[tid]       + gb[tid];
    float v1 = d1 * rstd * gs[tid + 256] + gb[tid + 256];
    float* yr = y + (size_t)t * DD;
    yr[tid]       = v0;
    yr[tid + 256] = v1;

    if (ohi) {
        int mtile = t >> 7, mrow = t & 127;
        #pragma unroll
        for (int half = 0; half < 2; half++) {
            int d = tid + half * 256;
            float v = half ? v1 : v0;
            __nv_bfloat16 h = __float2bfloat16(v);
            __nv_bfloat16 l = __float2bfloat16(v - __bfloat162float(h));
            int kc = d >> 5, ko = d & 31;
            size_t off = ((size_t)mtile * NKC + kc) * BLKB + mrow * 64 + ko * 2;
            *(__nv_bfloat16*)(ohi + off) = h;
            *(__nv_bfloat16*)(olo + off) = l;
        }
    }
}

// ---------------- coef: 64 tokens/block, weights staged in smem -------------
__global__ void __launch_bounds__(256)
k_coef(const float* __restrict__ hn,
       const float* __restrict__ pW, const float* __restrict__ pb,
       const float* __restrict__ aW, const float* __restrict__ ab) {
    __shared__ float sW[DD][20];
    int tid = threadIdx.x;

    for (int i = tid; i < DD * PP; i += 256) {
        int d = i >> 3, p = i & 7;
        sW[d][p]     = pW[i];
        sW[d][p + 8] = aW[i];
    }
    __syncthreads();

    int warp = tid >> 5, lane = tid & 31;
    #pragma unroll 1
    for (int tt = 0; tt < 8; tt++) {
        int t = blockIdx.x * 64 + warp * 8 + tt;
        const float* x = hn + (size_t)t * DD;
        float acc[16];
        #pragma unroll
        for (int p = 0; p < 16; p++) acc[p] = 0.f;

        #pragma unroll 4
        for (int i = 0; i < 16; i++) {
            int d = lane + i * 32;
            float xv = x[d];
            float4 w0 = *(const float4*)&sW[d][0];
            float4 w1 = *(const float4*)&sW[d][4];
            float4 w2 = *(const float4*)&sW[d][8];
            float4 w3 = *(const float4*)&sW[d][12];
            acc[0]  = fmaf(xv, w0.x, acc[0]);  acc[1]  = fmaf(xv, w0.y, acc[1]);
            acc[2]  = fmaf(xv, w0.z, acc[2]);  acc[3]  = fmaf(xv, w0.w, acc[3]);
            acc[4]  = fmaf(xv, w1.x, acc[4]);  acc[5]  = fmaf(xv, w1.y, acc[5]);
            acc[6]  = fmaf(xv, w1.z, acc[6]);  acc[7]  = fmaf(xv, w1.w, acc[7]);
            acc[8]  = fmaf(xv, w2.x, acc[8]);  acc[9]  = fmaf(xv, w2.y, acc[9]);
            acc[10] = fmaf(xv, w2.z, acc[10]); acc[11] = fmaf(xv, w2.w, acc[11]);
            acc[12] = fmaf(xv, w3.x, acc[12]); acc[13] = fmaf(xv, w3.y, acc[13]);
            acc[14] = fmaf(xv, w3.z, acc[14]); acc[15] = fmaf(xv, w3.w, acc[15]);
        }
        #pragma unroll
        for (int p = 0; p < 16; p++)
            #pragma unroll
            for (int o = 16; o; o >>= 1) acc[p] += __shfl_xor_sync(~0u, acc[p], o);

        if (lane == 0) {
            float c = 0.f;
            #pragma unroll
            for (int p = 0; p < PP; p++) {
                float ph = tanhf(acc[p] + pb[p]) * 3.14159265358979323846f;
                float av = acc[p + 8] + ab[p];
                float sp = (av > 20.f) ? av : log1pf(expf(av));
                float sc, cc;
                sincosf(ph, &sc, &cc);
                c += (sp + 0.1f) * (cc + sc);
            }
            g_coef[t] = c;
        }
    }
}

// ---------------- chunked cumsum over L (2 kernels) -------------------------
__global__ void k_chunksum() {
    int d = blockIdx.x * 128 + threadIdx.x;
    int ch = blockIdx.y, b = blockIdx.z;
    size_t base = ((size_t)(b * LL + ch * CHL)) * DD + d;
    float s = 0.f;
    #pragma unroll 8
    for (int l = 0; l < CHL; l++) s += g_val[base + (size_t)l * DD];
    g_csum[(b * NCH + ch) * DD + d] = s;
}

__global__ void k_scan() {   // per-block exclusive prefix + local scan
    int d = blockIdx.x * 128 + threadIdx.x;
    int ch = blockIdx.y, b = blockIdx.z;
    float acc = 0.f;
    for (int c = 0; c < ch; c++) acc += g_csum[(b * NCH + c) * DD + d];
    size_t base = ((size_t)(b * LL + ch * CHL)) * DD + d;
    const float inv = 0.0220970869120796089f;  // 1/sqrt(2048)
    #pragma unroll 8
    for (int l = 0; l < CHL; l++) {
        size_t i = base + (size_t)l * DD;
        acc += g_val[i];
        g_val[i] = acc * inv;
    }
}

// ---------------- bf16 split conversion: W [K, ldw] -> tile-chunked B -------
__global__ void k_convB(const float* __restrict__ W, int ldw,
                        unsigned char* __restrict__ dhi, unsigned char* __restrict__ dlo) {
    __shared__ float sm[32][132];
    int ntile = blockIdx.x, kc = blockIdx.y;
    int t = threadIdx.x;

    int n = t & 127, kh = t >> 7;
    #pragma unroll
    for (int j = 0; j < 16; j++) {
        int k = kh * 16 + j;
        sm[k][n] = W[(size_t)(kc * HKC + k) * ldw + ntile * HTN + n];
    }
    __syncthreads();

    int nr = t >> 1, kp = t & 1;
    __nv_bfloat16 hi[16], lo[16];
    #pragma unroll
    for (int j = 0; j < 16; j++) {
        float v = sm[kp * 16 + j][nr];
        __nv_bfloat16 h = __float2bfloat16(v);
        hi[j] = h;
        lo[j] = __float2bfloat16(v - __bfloat162float(h));
    }
    size_t blk = ((size_t)ntile * NKC + kc) * BLKB;
    uint32_t off = nr * 64 + kp * 32;
    *(uint4*)(dhi + blk + off)      = ((uint4*)hi)[0];
    *(uint4*)(dhi + blk + off + 16) = ((uint4*)hi)[1];
    *(uint4*)(dlo + blk + off)      = ((uint4*)lo)[0];
    *(uint4*)(dlo + blk + off + 16) = ((uint4*)lo)[1];
}

// ---------------- unified mma.sync bf16-split GEMM, 128x128 tile -------------
__global__ void __launch_bounds__(256)
k_mm(const unsigned char* __restrict__ Ahi_b, const unsigned char* __restrict__ Alo_b,
     const unsigned char* __restrict__ Bhi_b, const unsigned char* __restrict__ Blo_b,
     const float* __restrict__ bias, const float* __restrict__ rowscale,
     const float* __restrict__ add0, const float* __restrict__ add1,
     float* __restrict__ C, int ldc) {
    extern __shared__ __align__(16) unsigned char smx[];
    int tid = threadIdx.x, wid = tid >> 5, lane = tid & 31;
    int mtile = blockIdx.x, ntile = blockIdx.y;

    const unsigned char* srcs[4];
    srcs[0] = Ahi_b + (size_t)mtile * NKC * BLKB;
    srcs[1] = Alo_b + (size_t)mtile * NKC * BLKB;
    srcs[2] = Bhi_b + (size_t)ntile * NKC * BLKB;
    srcs[3] = Blo_b + (size_t)ntile * NKC * BLKB;

    uint32_t smbase = smem_u32(smx);

    auto copy_stage = [&](int s, int kc) {
        uint32_t dst0 = smbase + s * STG;
        #pragma unroll
        for (int m = 0; m < 4; m++) {
            const unsigned char* src = srcs[m] + (size_t)kc * BLKB;
            #pragma unroll
            for (int i = 0; i < 2; i++) {
                int q = i * 256 + tid;          // 512 quads of 16B per matrix
                int row = q >> 2, c = q & 3;
                cp16(dst0 + m * MATB + row * PRB + c * 16,
                     src + (size_t)q * 16);
            }
        }
        asm volatile("cp.async.commit_group;" ::: "memory");
    };

    float acc[4][4][4];
    #pragma unroll
    for (int i = 0; i < 4; i++)
        #pragma unroll
        for (int j = 0; j < 4; j++)
            #pragma unroll
            for (int q = 0; q < 4; q++) acc[i][j][q] = 0.f;

    int wm = (wid >> 2) * 64, wn = (wid & 3) * 32;

    // ldmatrix per-lane address components (byte offsets within a matrix)
    uint32_t aoff = (uint32_t)(wm + (lane & 15)) * PRB + ((lane >> 4) << 4);
    uint32_t boff = (uint32_t)(wn + (lane & 7)) * PRB + ((lane & 8) << 1);

    copy_stage(0, 0);
    copy_stage(1, 1);

    for (int kc = 0; kc < NKC; kc++) {
        int s = kc & 1;
        if (kc + 1 < NKC)
            asm volatile("cp.async.wait_group 1;" ::: "memory");
        else
            asm volatile("cp.async.wait_group 0;" ::: "memory");
        __syncthreads();

        uint32_t stA = smbase + s * STG;
        uint32_t aAh = stA + aoff;
        uint32_t aBh = stA + 2 * MATB + boff;

        #pragma unroll
        for (int kk = 0; kk < 2; kk++) {
            uint32_t kb = kk * 32;          // 16 bf16 = 32 bytes
            uint32_t ah[4][4], al[4][4], bh[4][2], bl[4][2];
            #pragma unroll
            for (int fm = 0; fm < 4; fm++) {
                ldsm4(aAh + fm * (16 * PRB) + kb, ah[fm]);
                ldsm4(aAh + MATB + fm * (16 * PRB) + kb, al[fm]);
            }
            #pragma unroll
            for (int fn = 0; fn < 4; fn++) {
                ldsm2(aBh + fn * (8 * PRB) + kb, bh[fn]);
                ldsm2(aBh + MATB + fn * (8 * PRB) + kb, bl[fn]);
            }
            #pragma unroll
            for (int fm = 0; fm < 4; fm++)
                #pragma unroll
                for (int fn = 0; fn < 4; fn++) {
                    MMA_BF16(acc[fm][fn], ah[fm], bh[fn]);
                    MMA_BF16(acc[fm][fn], ah[fm], bl[fn]);
                    MMA_BF16(acc[fm][fn], al[fm], bh[fn]);
                }
        }
        __syncthreads();
        if (kc + 2 < NKC) copy_stage(s, kc + 2);
    }

    // --- epilogue -----------------------------------------------------------
    int g = lane >> 2, tig = lane & 3;
    int orow0 = mtile * HTM + wm + g;
    int ocol0 = ntile * HTN + wn + tig * 2;
    #pragma unroll
    for (int fn = 0; fn < 4; fn++) {
        int c = ocol0 + fn * 8;
        float b0 = bias[c], b1 = bias[c + 1];
        #pragma unroll
        for (int fm = 0; fm < 4; fm++) {
            int r = orow0 + fm * 16;
            size_t i0 = (size_t)r * ldc + c;
            size_t i1 = (size_t)(r + 8) * ldc + c;
            float v00 = acc[fm][fn][0] + b0, v01 = acc[fm][fn][1] + b1;
            float v10 = acc[fm][fn][2] + b0, v11 = acc[fm][fn][3] + b1;
            if (rowscale) {
                float r0 = rowscale[r], r1 = rowscale[r + 8];
                v00 *= r0; v01 *= r0; v10 *= r1; v11 *= r1;
            }
            if (add0) {
                float2 a0 = *(const float2*)(add0 + i0);
                float2 a1 = *(const float2*)(add0 + i1);
                v00 += a0.x; v01 += a0.y; v10 += a1.x; v11 += a1.y;
            }
            if (add1) {
                float2 a0 = *(const float2*)(add1 + i0);
                float2 a1 = *(const float2*)(add1 + i1);
                v00 += a0.x; v01 += a0.y; v10 += a1.x; v11 += a1.y;
            }
            *(float2*)(C + i0) = make_float2(v00, v01);
            *(float2*)(C + i1) = make_float2(v10, v11);
        }
    }
}

// ---------------- launch ----------------------------------------------------
extern "C" void kernel_launch(void* const* d_in, const int* in_sizes, int n_in,
                              void* d_out, int out_size) {
    const int*   tokens        = (const int*)  d_in[0];
    const float* embed         = (const float*)d_in[1];
    const float* ln_scale      = (const float*)d_in[2];
    const float* ln_bias       = (const float*)d_in[3];
    const float* phase_W       = (const float*)d_in[4];
    const float* phase_b       = (const float*)d_in[5];
    const float* amp_W         = (const float*)d_in[6];
    const float* amp_b         = (const float*)d_in[7];
    const float* value_W       = (const float*)d_in[8];
    const float* value_b       = (const float*)d_in[9];
    const float* out_ln_scale  = (const float*)d_in[10];
    const float* out_ln_bias   = (const float*)d_in[11];
    const float* out_W         = (const float*)d_in[12];
    const float* out_b         = (const float*)d_in[13];
    const float* normout_scale = (const float*)d_in[14];
    const float* normout_bias  = (const float*)d_in[15];
    const float* head_W        = (const float*)d_in[16];
    const float* head_b        = (const float*)d_in[17];
    float* out = (float*)d_out;

    float *h, *hn, *val, *sn, *coef;
    unsigned char *whi, *wlo, *ahi, *alo, *lwhi, *lwlo;
    cudaGetSymbolAddress((void**)&h,    g_h);
    cudaGetSymbolAddress((void**)&hn,   g_hn);
    cudaGetSymbolAddress((void**)&val,  g_val);
    cudaGetSymbolAddress((void**)&sn,   g_sn);
    cudaGetSymbolAddress((void**)&coef, g_coef);
    cudaGetSymbolAddress((void**)&whi,  g_Whi);
    cudaGetSymbolAddress((void**)&wlo,  g_Wlo);
    cudaGetSymbolAddress((void**)&ahi,  g_Ahi);
    cudaGetSymbolAddress((void**)&alo,  g_Alo);
    cudaGetSymbolAddress((void**)&lwhi, g_LWhi);
    cudaGetSymbolAddress((void**)&lwlo, g_LWlo);

    cudaFuncSetAttribute(k_mm, cudaFuncAttributeMaxDynamicSharedMemorySize, SMEM_DYN);

    k_embed<<<TOK, 128>>>(tokens, embed);
    k_convB<<<dim3(HNT, NKC), 256>>>(head_W, VV, whi, wlo);
    size_t lwstep = (size_t)DD * DD * 2;
    for (int i = 0; i < NLAYER; i++) {
        k_convB<<<dim3(LNT, NKC), 256>>>(value_W + (size_t)i * DD * DD, DD,
                                         lwhi + (2*i+0)*lwstep, lwlo + (2*i+0)*lwstep);
        k_convB<<<dim3(LNT, NKC), 256>>>(out_W + (size_t)i * DD * DD, DD,
                                         lwhi + (2*i+1)*lwstep, lwlo + (2*i+1)*lwstep);
    }

    dim3 scanGrid(DD / 128, NCH, BB);
    dim3 mmLayer(HMT, LNT);

    for (int i = 0; i < NLAYER; i++) {
        k_ln<<<TOK, 256>>>(h, ln_scale + i * DD, ln_bias + i * DD, hn, ahi, alo);
        k_coef<<<TOK / 64, 256>>>(hn, phase_W + (size_t)i * DD * PP, phase_b + i * PP,
                                  amp_W + (size_t)i * DD * PP, amp_b + i * PP);
        k_mm<<<mmLayer, 256, SMEM_DYN>>>(ahi, alo,
                                         lwhi + (2*i+0)*lwstep, lwlo + (2*i+0)*lwstep,
                                         value_b + i * DD, coef, nullptr, nullptr,
                                         val, DD);
        k_chunksum<<<scanGrid, 128>>>();
        k_scan<<<scanGrid, 128>>>();
        k_ln<<<TOK, 256>>>(val, out_ln_scale + i * DD, out_ln_bias + i * DD, sn, ahi, alo);
        k_mm<<<mmLayer, 256, SMEM_DYN>>>(ahi, alo,
                                         lwhi + (2*i+1)*lwstep, lwlo + (2*i+1)*lwstep,
                                         out_b + i * DD, nullptr, h, hn,
                                         h, DD);
    }

    k_ln<<<TOK, 256>>>(h, normout_scale, normout_bias, hn, ahi, alo);
    k_mm<<<dim3(HMT, HNT), 256, SMEM_DYN>>>(ahi, alo, whi, wlo,
                                            head_b, nullptr, nullptr, nullptr,
                                            out, VV);
}

// round 6
// speedup vs baseline: 3.0108x; 1.2713x over previous
#include <cuda_runtime.h>
#include <cuda_fp16.h>
#include <math.h>
#include <stdint.h>

#define BB 2
#define LL 2048
#define DD 512
#define VV 32000
#define NLAYER 4
#define PP 8
#define TOK (BB*LL)           // 4096 tokens
#define NCH 16                // scan chunks along L
#define CHL (LL/NCH)          // 128

// ---- mma.sync GEMM geometry (shared by head + layer GEMMs) ----
#define HTM 128               // block tile M
#define HTN 128               // block tile N
#define HKC 32                // K per pipeline chunk (fp16)
#define NKC (DD/HKC)          // 16
#define HNT (VV/HTN)          // 250  (head)
#define LNT (DD/HTN)          // 4    (layer)
#define HMT (TOK/HTM)         // 32
#define BLKB (128*HKC*2)      // 8192 bytes per (tile,kchunk) operand block
#define PADROW 40             // fp16 per padded smem row (32 data + 8 pad)
#define PRB (PADROW*2)        // 80 bytes per padded row
#define MATB (128*PRB)        // 10240 bytes per padded matrix in smem
#define STG (3*MATB)          // 30720 per stage (Ah, Al, Bh)
#define SMEM_DYN (2*STG)      // 61440

// ---------------- scratch (device globals: no allocation allowed) -----------
__device__ float g_h [TOK*DD];
__device__ float g_hn[TOK*DD];
__device__ float g_val[TOK*DD];
__device__ float g_sn[TOK*DD];
__device__ float g_coef[TOK];
__device__ float g_csum[BB*NCH*DD];
// fp16 operands, tile-chunked layout
__device__ __align__(16) unsigned char g_Whi[(size_t)VV*DD*2];
__device__ __align__(16) unsigned char g_Ahi[(size_t)TOK*DD*2];
__device__ __align__(16) unsigned char g_Alo[(size_t)TOK*DD*2];
// layer weights: (layer, {value,out}, ntile, kc) blocks
__device__ __align__(16) unsigned char g_LWhi[(size_t)NLAYER*2*DD*DD*2];

// ---------------- helpers ----------------------------------------------------
__device__ __forceinline__ uint32_t smem_u32(const void* p) {
    uint32_t a;
    asm("{ .reg .u64 t; cvta.to.shared.u64 t, %1; cvt.u32.u64 %0, t; }"
        : "=r"(a) : "l"(p));
    return a;
}

__device__ __forceinline__ void cp16(uint32_t dst, const void* src) {
    asm volatile("cp.async.cg.shared.global [%0], [%1], 16;"
                 :: "r"(dst), "l"(src) : "memory");
}

__device__ __forceinline__ void ldsm4(uint32_t addr, uint32_t* r) {
    asm volatile("ldmatrix.sync.aligned.m8n8.x4.shared.b16 {%0,%1,%2,%3}, [%4];"
        : "=r"(r[0]), "=r"(r[1]), "=r"(r[2]), "=r"(r[3]) : "r"(addr));
}
__device__ __forceinline__ void ldsm2(uint32_t addr, uint32_t* r) {
    asm volatile("ldmatrix.sync.aligned.m8n8.x2.shared.b16 {%0,%1}, [%2];"
        : "=r"(r[0]), "=r"(r[1]) : "r"(addr));
}

#define MMA_F16(d, a, b) \
    asm volatile("mma.sync.aligned.m16n8k16.row.col.f32.f16.f16.f32 " \
        "{%0,%1,%2,%3},{%4,%5,%6,%7},{%8,%9},{%0,%1,%2,%3};" \
        : "+f"((d)[0]), "+f"((d)[1]), "+f"((d)[2]), "+f"((d)[3]) \
        : "r"((a)[0]), "r"((a)[1]), "r"((a)[2]), "r"((a)[3]), \
          "r"((b)[0]), "r"((b)[1]))

// ---------------- embedding gather ------------------------------------------
__global__ void k_embed(const int* __restrict__ tok, const float* __restrict__ emb) {
    int t = blockIdx.x;
    int tk = tok[t];
    const float4* src = (const float4*)(emb + (size_t)tk * DD);
    float4* dst = (float4*)(g_h + (size_t)t * DD);
    dst[threadIdx.x] = src[threadIdx.x];
}

// ---------------- LayerNorm + fused fp16 hi/lo split output -----------------
__global__ void k_ln(const float* __restrict__ x, const float* __restrict__ gs,
                     const float* __restrict__ gb, float* __restrict__ y,
                     unsigned char* __restrict__ ohi, unsigned char* __restrict__ olo) {
    int t = blockIdx.x;
    int tid = threadIdx.x;
    __shared__ float red[8];

    const float* xr = x + (size_t)t * DD;
    float a = xr[tid];
    float b = xr[tid + 256];

    float s = a + b;
    #pragma unroll
    for (int o = 16; o; o >>= 1) s += __shfl_xor_sync(~0u, s, o);
    if ((tid & 31) == 0) red[tid >> 5] = s;
    __syncthreads();
    if (tid == 0) { float r = 0; for (int i = 0; i < 8; i++) r += red[i]; red[0] = r * (1.0f / DD); }
    __syncthreads();
    float mean = red[0];
    __syncthreads();

    float d0 = a - mean, d1 = b - mean;
    float s2 = d0 * d0 + d1 * d1;
    #pragma unroll
    for (int o = 16; o; o >>= 1) s2 += __shfl_xor_sync(~0u, s2, o);
    if ((tid & 31) == 0) red[tid >> 5] = s2;
    __syncthreads();
    if (tid == 0) { float r = 0; for (int i = 0; i < 8; i++) r += red[i]; red[0] = rsqrtf(r * (1.0f / DD) + 1e-5f); }
    __syncthreads();
    float rstd = red[0];

    float v0 = d0 * rstd * gs[tid]       + gb[tid];
    float v1 = d1 * rstd * gs[tid + 256] + gb[tid + 256];
    float* yr = y + (size_t)t * DD;
    yr[tid]       = v0;
    yr[tid + 256] = v1;

    if (ohi) {
        int mtile = t >> 7, mrow = t & 127;
        #pragma unroll
        for (int half = 0; half < 2; half++) {
            int d = tid + half * 256;
            float v = half ? v1 : v0;
            __half h = __float2half(v);
            __half l = __float2half(v - __half2float(h));
            int kc = d >> 5, ko = d & 31;
            size_t off = ((size_t)mtile * NKC + kc) * BLKB + mrow * 64 + ko * 2;
            *(__half*)(ohi + off) = h;
            *(__half*)(olo + off) = l;
        }
    }
}

// ---------------- coef: 64 tokens/block, weights staged in smem -------------
__global__ void __launch_bounds__(256)
k_coef(const float* __restrict__ hn,
       const float* __restrict__ pW, const float* __restrict__ pb,
       const float* __restrict__ aW, const float* __restrict__ ab) {
    __shared__ float sW[DD][20];
    int tid = threadIdx.x;

    for (int i = tid; i < DD * PP; i += 256) {
        int d = i >> 3, p = i & 7;
        sW[d][p]     = pW[i];
        sW[d][p + 8] = aW[i];
    }
    __syncthreads();

    int warp = tid >> 5, lane = tid & 31;
    #pragma unroll 1
    for (int tt = 0; tt < 8; tt++) {
        int t = blockIdx.x * 64 + warp * 8 + tt;
        const float* x = hn + (size_t)t * DD;
        float acc[16];
        #pragma unroll
        for (int p = 0; p < 16; p++) acc[p] = 0.f;

        #pragma unroll 4
        for (int i = 0; i < 16; i++) {
            int d = lane + i * 32;
            float xv = x[d];
            float4 w0 = *(const float4*)&sW[d][0];
            float4 w1 = *(const float4*)&sW[d][4];
            float4 w2 = *(const float4*)&sW[d][8];
            float4 w3 = *(const float4*)&sW[d][12];
            acc[0]  = fmaf(xv, w0.x, acc[0]);  acc[1]  = fmaf(xv, w0.y, acc[1]);
            acc[2]  = fmaf(xv, w0.z, acc[2]);  acc[3]  = fmaf(xv, w0.w, acc[3]);
            acc[4]  = fmaf(xv, w1.x, acc[4]);  acc[5]  = fmaf(xv, w1.y, acc[5]);
            acc[6]  = fmaf(xv, w1.z, acc[6]);  acc[7]  = fmaf(xv, w1.w, acc[7]);
            acc[8]  = fmaf(xv, w2.x, acc[8]);  acc[9]  = fmaf(xv, w2.y, acc[9]);
            acc[10] = fmaf(xv, w2.z, acc[10]); acc[11] = fmaf(xv, w2.w, acc[11]);
            acc[12] = fmaf(xv, w3.x, acc[12]); acc[13] = fmaf(xv, w3.y, acc[13]);
            acc[14] = fmaf(xv, w3.z, acc[14]); acc[15] = fmaf(xv, w3.w, acc[15]);
        }
        #pragma unroll
        for (int p = 0; p < 16; p++)
            #pragma unroll
            for (int o = 16; o; o >>= 1) acc[p] += __shfl_xor_sync(~0u, acc[p], o);

        if (lane == 0) {
            float c = 0.f;
            #pragma unroll
            for (int p = 0; p < PP; p++) {
                float ph = tanhf(acc[p] + pb[p]) * 3.14159265358979323846f;
                float av = acc[p + 8] + ab[p];
                float sp = (av > 20.f) ? av : log1pf(expf(av));
                float sc, cc;
                sincosf(ph, &sc, &cc);
                c += (sp + 0.1f) * (cc + sc);
            }
            g_coef[t] = c;
        }
    }
}

// ---------------- chunked cumsum over L (2 kernels) -------------------------
__global__ void k_chunksum() {
    int d = blockIdx.x * 128 + threadIdx.x;
    int ch = blockIdx.y, b = blockIdx.z;
    size_t base = ((size_t)(b * LL + ch * CHL)) * DD + d;
    float s = 0.f;
    #pragma unroll 8
    for (int l = 0; l < CHL; l++) s += g_val[base + (size_t)l * DD];
    g_csum[(b * NCH + ch) * DD + d] = s;
}

__global__ void k_scan() {   // per-block exclusive prefix + local scan
    int d = blockIdx.x * 128 + threadIdx.x;
    int ch = blockIdx.y, b = blockIdx.z;
    float acc = 0.f;
    for (int c = 0; c < ch; c++) acc += g_csum[(b * NCH + c) * DD + d];
    size_t base = ((size_t)(b * LL + ch * CHL)) * DD + d;
    const float inv = 0.0220970869120796089f;  // 1/sqrt(2048)
    #pragma unroll 8
    for (int l = 0; l < CHL; l++) {
        size_t i = base + (size_t)l * DD;
        acc += g_val[i];
        g_val[i] = acc * inv;
    }
}

// ---------------- fp16 conversion: W [K, ldw] -> tile-chunked B (hi only) ---
__global__ void k_convB(const float* __restrict__ W, int ldw,
                        unsigned char* __restrict__ dhi) {
    __shared__ float sm[32][132];
    int ntile = blockIdx.x, kc = blockIdx.y;
    int t = threadIdx.x;

    int n = t & 127, kh = t >> 7;
    #pragma unroll
    for (int j = 0; j < 16; j++) {
        int k = kh * 16 + j;
        sm[k][n] = W[(size_t)(kc * HKC + k) * ldw + ntile * HTN + n];
    }
    __syncthreads();

    int nr = t >> 1, kp = t & 1;
    __half hi[16];
    #pragma unroll
    for (int j = 0; j < 16; j++)
        hi[j] = __float2half(sm[kp * 16 + j][nr]);
    size_t blk = ((size_t)ntile * NKC + kc) * BLKB;
    uint32_t off = nr * 64 + kp * 32;
    *(uint4*)(dhi + blk + off)      = ((uint4*)hi)[0];
    *(uint4*)(dhi + blk + off + 16) = ((uint4*)hi)[1];
}

// ---------------- unified mma.sync fp16 2-term GEMM, 128x128 tile ------------
__global__ void __launch_bounds__(256)
k_mm(const unsigned char* __restrict__ Ahi_b, const unsigned char* __restrict__ Alo_b,
     const unsigned char* __restrict__ Bhi_b,
     const float* __restrict__ bias, const float* __restrict__ rowscale,
     const float* __restrict__ add0, const float* __restrict__ add1,
     float* __restrict__ C, int ldc) {
    extern __shared__ __align__(16) unsigned char smx[];
    int tid = threadIdx.x, wid = tid >> 5, lane = tid & 31;
    int mtile = blockIdx.x, ntile = blockIdx.y;

    const unsigned char* srcs[3];
    srcs[0] = Ahi_b + (size_t)mtile * NKC * BLKB;
    srcs[1] = Alo_b + (size_t)mtile * NKC * BLKB;
    srcs[2] = Bhi_b + (size_t)ntile * NKC * BLKB;

    uint32_t smbase = smem_u32(smx);

    auto copy_stage = [&](int s, int kc) {
        uint32_t dst0 = smbase + s * STG;
        #pragma unroll
        for (int m = 0; m < 3; m++) {
            const unsigned char* src = srcs[m] + (size_t)kc * BLKB;
            #pragma unroll
            for (int i = 0; i < 2; i++) {
                int q = i * 256 + tid;          // 512 quads of 16B per matrix
                int row = q >> 2, c = q & 3;
                cp16(dst0 + m * MATB + row * PRB + c * 16,
                     src + (size_t)q * 16);
            }
        }
        asm volatile("cp.async.commit_group;" ::: "memory");
    };

    float acc[4][4][4];
    #pragma unroll
    for (int i = 0; i < 4; i++)
        #pragma unroll
        for (int j = 0; j < 4; j++)
            #pragma unroll
            for (int q = 0; q < 4; q++) acc[i][j][q] = 0.f;

    int wm = (wid >> 2) * 64, wn = (wid & 3) * 32;

    // ldmatrix per-lane address components (byte offsets within a matrix)
    uint32_t aoff = (uint32_t)(wm + (lane & 15)) * PRB + ((lane >> 4) << 4);
    uint32_t boff = (uint32_t)(wn + (lane & 7)) * PRB + ((lane & 8) << 1);

    copy_stage(0, 0);
    copy_stage(1, 1);

    for (int kc = 0; kc < NKC; kc++) {
        int s = kc & 1;
        if (kc + 1 < NKC)
            asm volatile("cp.async.wait_group 1;" ::: "memory");
        else
            asm volatile("cp.async.wait_group 0;" ::: "memory");
        __syncthreads();

        uint32_t stA = smbase + s * STG;
        uint32_t aAh = stA + aoff;
        uint32_t aBh = stA + 2 * MATB + boff;

        #pragma unroll
        for (int kk = 0; kk < 2; kk++) {
            uint32_t kb = kk * 32;          // 16 fp16 = 32 bytes
            uint32_t ah[4][4], al[4][4], bh[4][2];
            #pragma unroll
            for (int fm = 0; fm < 4; fm++) {
                ldsm4(aAh + fm * (16 * PRB) + kb, ah[fm]);
                ldsm4(aAh + MATB + fm * (16 * PRB) + kb, al[fm]);
            }
            #pragma unroll
            for (int fn = 0; fn < 4; fn++)
                ldsm2(aBh + fn * (8 * PRB) + kb, bh[fn]);
            #pragma unroll
            for (int fm = 0; fm < 4; fm++)
                #pragma unroll
                for (int fn = 0; fn < 4; fn++) {
                    MMA_F16(acc[fm][fn], ah[fm], bh[fn]);
                    MMA_F16(acc[fm][fn], al[fm], bh[fn]);
                }
        }
        __syncthreads();
        if (kc + 2 < NKC) copy_stage(s, kc + 2);
    }

    // --- epilogue -----------------------------------------------------------
    int g = lane >> 2, tig = lane & 3;
    int orow0 = mtile * HTM + wm + g;
    int ocol0 = ntile * HTN + wn + tig * 2;
    #pragma unroll
    for (int fn = 0; fn < 4; fn++) {
        int c = ocol0 + fn * 8;
        float b0 = bias[c], b1 = bias[c + 1];
        #pragma unroll
        for (int fm = 0; fm < 4; fm++) {
            int r = orow0 + fm * 16;
            size_t i0 = (size_t)r * ldc + c;
            size_t i1 = (size_t)(r + 8) * ldc + c;
            float v00 = acc[fm][fn][0] + b0, v01 = acc[fm][fn][1] + b1;
            float v10 = acc[fm][fn][2] + b0, v11 = acc[fm][fn][3] + b1;
            if (rowscale) {
                float r0 = rowscale[r], r1 = rowscale[r + 8];
                v00 *= r0; v01 *= r0; v10 *= r1; v11 *= r1;
            }
            if (add0) {
                float2 a0 = *(const float2*)(add0 + i0);
                float2 a1 = *(const float2*)(add0 + i1);
                v00 += a0.x; v01 += a0.y; v10 += a1.x; v11 += a1.y;
            }
            if (add1) {
                float2 a0 = *(const float2*)(add1 + i0);
                float2 a1 = *(const float2*)(add1 + i1);
                v00 += a0.x; v01 += a0.y; v10 += a1.x; v11 += a1.y;
            }
            *(float2*)(C + i0) = make_float2(v00, v01);
            *(float2*)(C + i1) = make_float2(v10, v11);
        }
    }
}

// ---------------- launch ----------------------------------------------------
extern "C" void kernel_launch(void* const* d_in, const int* in_sizes, int n_in,
                              void* d_out, int out_size) {
    const int*   tokens        = (const int*)  d_in[0];
    const float* embed         = (const float*)d_in[1];
    const float* ln_scale      = (const float*)d_in[2];
    const float* ln_bias       = (const float*)d_in[3];
    const float* phase_W       = (const float*)d_in[4];
    const float* phase_b       = (const float*)d_in[5];
    const float* amp_W         = (const float*)d_in[6];
    const float* amp_b         = (const float*)d_in[7];
    const float* value_W       = (const float*)d_in[8];
    const float* value_b       = (const float*)d_in[9];
    const float* out_ln_scale  = (const float*)d_in[10];
    const float* out_ln_bias   = (const float*)d_in[11];
    const float* out_W         = (const float*)d_in[12];
    const float* out_b         = (const float*)d_in[13];
    const float* normout_scale = (const float*)d_in[14];
    const float* normout_bias  = (const float*)d_in[15];
    const float* head_W        = (const float*)d_in[16];
    const float* head_b        = (const float*)d_in[17];
    float* out = (float*)d_out;

    float *h, *hn, *val, *sn, *coef;
    unsigned char *whi, *ahi, *alo, *lwhi;
    cudaGetSymbolAddress((void**)&h,    g_h);
    cudaGetSymbolAddress((void**)&hn,   g_hn);
    cudaGetSymbolAddress((void**)&val,  g_val);
    cudaGetSymbolAddress((void**)&sn,   g_sn);
    cudaGetSymbolAddress((void**)&coef, g_coef);
    cudaGetSymbolAddress((void**)&whi,  g_Whi);
    cudaGetSymbolAddress((void**)&ahi,  g_Ahi);
    cudaGetSymbolAddress((void**)&alo,  g_Alo);
    cudaGetSymbolAddress((void**)&lwhi, g_LWhi);

    cudaFuncSetAttribute(k_mm, cudaFuncAttributeMaxDynamicSharedMemorySize, SMEM_DYN);

    k_embed<<<TOK, 128>>>(tokens, embed);
    k_convB<<<dim3(HNT, NKC), 256>>>(head_W, VV, whi);
    size_t lwstep = (size_t)DD * DD * 2;
    for (int i = 0; i < NLAYER; i++) {
        k_convB<<<dim3(LNT, NKC), 256>>>(value_W + (size_t)i * DD * DD, DD,
                                         lwhi + (2*i+0)*lwstep);
        k_convB<<<dim3(LNT, NKC), 256>>>(out_W + (size_t)i * DD * DD, DD,
                                         lwhi + (2*i+1)*lwstep);
    }

    dim3 scanGrid(DD / 128, NCH, BB);
    dim3 mmLayer(HMT, LNT);

    for (int i = 0; i < NLAYER; i++) {
        k_ln<<<TOK, 256>>>(h, ln_scale + i * DD, ln_bias + i * DD, hn, ahi, alo);
        k_coef<<<TOK / 64, 256>>>(hn, phase_W + (size_t)i * DD * PP, phase_b + i * PP,
                                  amp_W + (size_t)i * DD * PP, amp_b + i * PP);
        k_mm<<<mmLayer, 256, SMEM_DYN>>>(ahi, alo, lwhi + (2*i+0)*lwstep,
                                         value_b + i * DD, coef, nullptr, nullptr,
                                         val, DD);
        k_chunksum<<<scanGrid, 128>>>();
        k_scan<<<scanGrid, 128>>>();
        k_ln<<<TOK, 256>>>(val, out_ln_scale + i * DD, out_ln_bias + i * DD, sn, ahi, alo);
        k_mm<<<mmLayer, 256, SMEM_DYN>>>(ahi, alo, lwhi + (2*i+1)*lwstep,
                                         out_b + i * DD, nullptr, h, hn,
                                         h, DD);
    }

    k_ln<<<TOK, 256>>>(h, normout_scale, normout_bias, hn, ahi, alo);
    k_mm<<<dim3(HMT, HNT), 256, SMEM_DYN>>>(ahi, alo, whi,
                                            head_b, nullptr, nullptr, nullptr,
                                            out, VV);
}

// round 7
// speedup vs baseline: 3.8687x; 1.2849x over previous
#include <cuda_runtime.h>
#include <cuda_fp16.h>
#include <math.h>
#include <stdint.h>

#define BB 2
#define LL 2048
#define DD 512
#define VV 32000
#define NLAYER 4
#define PP 8
#define TOK (BB*LL)           // 4096 tokens
#define NCH 16                // scan chunks along L
#define CHL (LL/NCH)          // 128

// ---- mma.sync GEMM geometry (shared by head + layer GEMMs) ----
#define HTM 128               // block tile M
#define HTN 128               // block tile N
#define HKC 32                // K per pipeline chunk (fp16)
#define NKC (DD/HKC)          // 16
#define HNT (VV/HTN)          // 250  (head)
#define LNT (DD/HTN)          // 4    (layer)
#define HMT (TOK/HTM)         // 32
#define BLKB (128*HKC*2)      // 8192 bytes per (tile,kchunk) operand block
#define PADROW 40             // fp16 per padded smem row (32 data + 8 pad)
#define PRB (PADROW*2)        // 80 bytes per padded row
#define MATB (128*PRB)        // 10240 bytes per padded matrix in smem
#define STG (3*MATB)          // 30720 per stage (Ah, Al, Bh)
#define SMEM_DYN (2*STG)      // 61440

// ---------------- scratch (device globals: no allocation allowed) -----------
__device__ float g_h [TOK*DD];
__device__ float g_hn[TOK*DD];
__device__ float g_val[TOK*DD];
__device__ float g_sn[TOK*DD];
__device__ float g_coef[TOK];
__device__ float g_csum[BB*NCH*DD];
// fp16 operands, tile-chunked layout
__device__ __align__(16) unsigned char g_Whi[(size_t)VV*DD*2];
__device__ __align__(16) unsigned char g_Ahi[(size_t)TOK*DD*2];
__device__ __align__(16) unsigned char g_Alo[(size_t)TOK*DD*2];
// layer weights: (layer, {value,out}, ntile, kc) blocks
__device__ __align__(16) unsigned char g_LWhi[(size_t)NLAYER*2*DD*DD*2];

// ---------------- helpers ----------------------------------------------------
__device__ __forceinline__ uint32_t smem_u32(const void* p) {
    uint32_t a;
    asm("{ .reg .u64 t; cvta.to.shared.u64 t, %1; cvt.u32.u64 %0, t; }"
        : "=r"(a) : "l"(p));
    return a;
}

__device__ __forceinline__ void cp16(uint32_t dst, const void* src) {
    asm volatile("cp.async.cg.shared.global [%0], [%1], 16;"
                 :: "r"(dst), "l"(src) : "memory");
}

__device__ __forceinline__ void ldsm4(uint32_t addr, uint32_t* r) {
    asm volatile("ldmatrix.sync.aligned.m8n8.x4.shared.b16 {%0,%1,%2,%3}, [%4];"
        : "=r"(r[0]), "=r"(r[1]), "=r"(r[2]), "=r"(r[3]) : "r"(addr));
}
__device__ __forceinline__ void ldsm2(uint32_t addr, uint32_t* r) {
    asm volatile("ldmatrix.sync.aligned.m8n8.x2.shared.b16 {%0,%1}, [%2];"
        : "=r"(r[0]), "=r"(r[1]) : "r"(addr));
}

#define MMA_F16(d, a, b) \
    asm volatile("mma.sync.aligned.m16n8k16.row.col.f32.f16.f16.f32 " \
        "{%0,%1,%2,%3},{%4,%5,%6,%7},{%8,%9},{%0,%1,%2,%3};" \
        : "+f"((d)[0]), "+f"((d)[1]), "+f"((d)[2]), "+f"((d)[3]) \
        : "r"((a)[0]), "r"((a)[1]), "r"((a)[2]), "r"((a)[3]), \
          "r"((b)[0]), "r"((b)[1]))

// ---------------- embedding gather ------------------------------------------
__global__ void k_embed(const int* __restrict__ tok, const float* __restrict__ emb) {
    int t = blockIdx.x;
    int tk = tok[t];
    const float4* src = (const float4*)(emb + (size_t)tk * DD);
    float4* dst = (float4*)(g_h + (size_t)t * DD);
    dst[threadIdx.x] = src[threadIdx.x];
}

// ---------------- LayerNorm + fused fp16 hi/lo split output -----------------
__global__ void k_ln(const float* __restrict__ x, const float* __restrict__ gs,
                     const float* __restrict__ gb, float* __restrict__ y,
                     unsigned char* __restrict__ ohi, unsigned char* __restrict__ olo) {
    int t = blockIdx.x;
    int tid = threadIdx.x;
    __shared__ float red[8];

    const float* xr = x + (size_t)t * DD;
    float a = xr[tid];
    float b = xr[tid + 256];

    float s = a + b;
    #pragma unroll
    for (int o = 16; o; o >>= 1) s += __shfl_xor_sync(~0u, s, o);
    if ((tid & 31) == 0) red[tid >> 5] = s;
    __syncthreads();
    if (tid == 0) { float r = 0; for (int i = 0; i < 8; i++) r += red[i]; red[0] = r * (1.0f / DD); }
    __syncthreads();
    float mean = red[0];
    __syncthreads();

    float d0 = a - mean, d1 = b - mean;
    float s2 = d0 * d0 + d1 * d1;
    #pragma unroll
    for (int o = 16; o; o >>= 1) s2 += __shfl_xor_sync(~0u, s2, o);
    if ((tid & 31) == 0) red[tid >> 5] = s2;
    __syncthreads();
    if (tid == 0) { float r = 0; for (int i = 0; i < 8; i++) r += red[i]; red[0] = rsqrtf(r * (1.0f / DD) + 1e-5f); }
    __syncthreads();
    float rstd = red[0];

    float v0 = d0 * rstd * gs[tid]       + gb[tid];
    float v1 = d1 * rstd * gs[tid + 256] + gb[tid + 256];
    float* yr = y + (size_t)t * DD;
    yr[tid]       = v0;
    yr[tid + 256] = v1;

    if (ohi) {
        int mtile = t >> 7, mrow = t & 127;
        #pragma unroll
        for (int half = 0; half < 2; half++) {
            int d = tid + half * 256;
            float v = half ? v1 : v0;
            __half h = __float2half(v);
            __half l = __float2half(v - __half2float(h));
            int kc = d >> 5, ko = d & 31;
            size_t off = ((size_t)mtile * NKC + kc) * BLKB + mrow * 64 + ko * 2;
            *(__half*)(ohi + off) = h;
            *(__half*)(olo + off) = l;
        }
    }
}

// ---------------- coef: 64 tokens/block, weights staged in smem -------------
__global__ void __launch_bounds__(256)
k_coef(const float* __restrict__ hn,
       const float* __restrict__ pW, const float* __restrict__ pb,
       const float* __restrict__ aW, const float* __restrict__ ab) {
    __shared__ float sW[DD][20];
    int tid = threadIdx.x;

    for (int i = tid; i < DD * PP; i += 256) {
        int d = i >> 3, p = i & 7;
        sW[d][p]     = pW[i];
        sW[d][p + 8] = aW[i];
    }
    __syncthreads();

    int warp = tid >> 5, lane = tid & 31;
    #pragma unroll 1
    for (int tt = 0; tt < 8; tt++) {
        int t = blockIdx.x * 64 + warp * 8 + tt;
        const float* x = hn + (size_t)t * DD;
        float acc[16];
        #pragma unroll
        for (int p = 0; p < 16; p++) acc[p] = 0.f;

        #pragma unroll 4
        for (int i = 0; i < 16; i++) {
            int d = lane + i * 32;
            float xv = x[d];
            float4 w0 = *(const float4*)&sW[d][0];
            float4 w1 = *(const float4*)&sW[d][4];
            float4 w2 = *(const float4*)&sW[d][8];
            float4 w3 = *(const float4*)&sW[d][12];
            acc[0]  = fmaf(xv, w0.x, acc[0]);  acc[1]  = fmaf(xv, w0.y, acc[1]);
            acc[2]  = fmaf(xv, w0.z, acc[2]);  acc[3]  = fmaf(xv, w0.w, acc[3]);
            acc[4]  = fmaf(xv, w1.x, acc[4]);  acc[5]  = fmaf(xv, w1.y, acc[5]);
            acc[6]  = fmaf(xv, w1.z, acc[6]);  acc[7]  = fmaf(xv, w1.w, acc[7]);
            acc[8]  = fmaf(xv, w2.x, acc[8]);  acc[9]  = fmaf(xv, w2.y, acc[9]);
            acc[10] = fmaf(xv, w2.z, acc[10]); acc[11] = fmaf(xv, w2.w, acc[11]);
            acc[12] = fmaf(xv, w3.x, acc[12]); acc[13] = fmaf(xv, w3.y, acc[13]);
            acc[14] = fmaf(xv, w3.z, acc[14]); acc[15] = fmaf(xv, w3.w, acc[15]);
        }
        #pragma unroll
        for (int p = 0; p < 16; p++)
            #pragma unroll
            for (int o = 16; o; o >>= 1) acc[p] += __shfl_xor_sync(~0u, acc[p], o);

        if (lane == 0) {
            float c = 0.f;
            #pragma unroll
            for (int p = 0; p < PP; p++) {
                float ph = tanhf(acc[p] + pb[p]) * 3.14159265358979323846f;
                float av = acc[p + 8] + ab[p];
                float sp = (av > 20.f) ? av : log1pf(expf(av));
                float sc, cc;
                sincosf(ph, &sc, &cc);
                c += (sp + 0.1f) * (cc + sc);
            }
            g_coef[t] = c;
        }
    }
}

// ---------------- scan (chunk sums come fused from value GEMM) --------------
__global__ void k_scan() {   // per-block exclusive prefix + local scan
    int d = blockIdx.x * 128 + threadIdx.x;
    int ch = blockIdx.y, b = blockIdx.z;
    float acc = 0.f;
    for (int c = 0; c < ch; c++) acc += g_csum[(b * NCH + c) * DD + d];
    size_t base = ((size_t)(b * LL + ch * CHL)) * DD + d;
    const float inv = 0.0220970869120796089f;  // 1/sqrt(2048)
    #pragma unroll 8
    for (int l = 0; l < CHL; l++) {
        size_t i = base + (size_t)l * DD;
        acc += g_val[i];
        g_val[i] = acc * inv;
    }
}

// ---------------- fp16 conversion: W [K, ldw] -> tile-chunked B (hi only) ---
__global__ void k_convB(const float* __restrict__ W, int ldw,
                        unsigned char* __restrict__ dhi) {
    __shared__ float sm[32][132];
    int ntile = blockIdx.x, kc = blockIdx.y;
    int t = threadIdx.x;

    int n = t & 127, kh = t >> 7;
    #pragma unroll
    for (int j = 0; j < 16; j++) {
        int k = kh * 16 + j;
        sm[k][n] = W[(size_t)(kc * HKC + k) * ldw + ntile * HTN + n];
    }
    __syncthreads();

    int nr = t >> 1, kp = t & 1;
    __half hi[16];
    #pragma unroll
    for (int j = 0; j < 16; j++)
        hi[j] = __float2half(sm[kp * 16 + j][nr]);
    size_t blk = ((size_t)ntile * NKC + kc) * BLKB;
    uint32_t off = nr * 64 + kp * 32;
    *(uint4*)(dhi + blk + off)      = ((uint4*)hi)[0];
    *(uint4*)(dhi + blk + off + 16) = ((uint4*)hi)[1];
}

// ---------------- unified mma.sync fp16 GEMM, 128x128 tile -------------------
// TWOTERM: D = Ah*Bh + Al*Bh  (else Ah*Bh only)
// CSUM:    also writes per-block column sums of final v into g_csum
template<bool TWOTERM, bool CSUM>
__global__ void __launch_bounds__(256)
k_mm(const unsigned char* __restrict__ Ahi_b, const unsigned char* __restrict__ Alo_b,
     const unsigned char* __restrict__ Bhi_b,
     const float* __restrict__ bias, const float* __restrict__ rowscale,
     const float* __restrict__ add0, const float* __restrict__ add1,
     float* __restrict__ C, int ldc) {
    extern __shared__ __align__(16) unsigned char smx[];
    __shared__ float s_cs[2][128];
    int tid = threadIdx.x, wid = tid >> 5, lane = tid & 31;
    int mtile = blockIdx.x, ntile = blockIdx.y;

    const unsigned char* srcA = Ahi_b + (size_t)mtile * NKC * BLKB;
    const unsigned char* srcL = TWOTERM ? (Alo_b + (size_t)mtile * NKC * BLKB) : nullptr;
    const unsigned char* srcB = Bhi_b + (size_t)ntile * NKC * BLKB;

    uint32_t smbase = smem_u32(smx);

    auto copy_stage = [&](int s, int kc) {
        uint32_t dst0 = smbase + s * STG;
        #pragma unroll
        for (int i = 0; i < 2; i++) {
            int q = i * 256 + tid;          // 512 quads of 16B per matrix
            int row = q >> 2, c = q & 3;
            uint32_t doff = row * PRB + c * 16;
            cp16(dst0 + doff, srcA + (size_t)kc * BLKB + (size_t)q * 16);
            if (TWOTERM)
                cp16(dst0 + MATB + doff, srcL + (size_t)kc * BLKB + (size_t)q * 16);
            cp16(dst0 + 2 * MATB + doff, srcB + (size_t)kc * BLKB + (size_t)q * 16);
        }
        asm volatile("cp.async.commit_group;" ::: "memory");
    };

    float acc[4][4][4];
    #pragma unroll
    for (int i = 0; i < 4; i++)
        #pragma unroll
        for (int j = 0; j < 4; j++)
            #pragma unroll
            for (int q = 0; q < 4; q++) acc[i][j][q] = 0.f;

    int wm = (wid >> 2) * 64, wn = (wid & 3) * 32;

    uint32_t aoff = (uint32_t)(wm + (lane & 15)) * PRB + ((lane >> 4) << 4);
    uint32_t boff = (uint32_t)(wn + (lane & 7)) * PRB + ((lane & 8) << 1);

    copy_stage(0, 0);
    copy_stage(1, 1);

    for (int kc = 0; kc < NKC; kc++) {
        int s = kc & 1;
        if (kc + 1 < NKC)
            asm volatile("cp.async.wait_group 1;" ::: "memory");
        else
            asm volatile("cp.async.wait_group 0;" ::: "memory");
        __syncthreads();

        uint32_t stA = smbase + s * STG;
        uint32_t aAh = stA + aoff;
        uint32_t aBh = stA + 2 * MATB + boff;

        #pragma unroll
        for (int kk = 0; kk < 2; kk++) {
            uint32_t kb = kk * 32;          // 16 fp16 = 32 bytes
            uint32_t ah[4][4], al[4][4], bh[4][2];
            #pragma unroll
            for (int fm = 0; fm < 4; fm++) {
                ldsm4(aAh + fm * (16 * PRB) + kb, ah[fm]);
                if (TWOTERM) ldsm4(aAh + MATB + fm * (16 * PRB) + kb, al[fm]);
            }
            #pragma unroll
            for (int fn = 0; fn < 4; fn++)
                ldsm2(aBh + fn * (8 * PRB) + kb, bh[fn]);
            #pragma unroll
            for (int fm = 0; fm < 4; fm++)
                #pragma unroll
                for (int fn = 0; fn < 4; fn++) {
                    MMA_F16(acc[fm][fn], ah[fm], bh[fn]);
                    if (TWOTERM) MMA_F16(acc[fm][fn], al[fm], bh[fn]);
                }
        }
        __syncthreads();
        if (kc + 2 < NKC) copy_stage(s, kc + 2);
    }

    // --- epilogue -----------------------------------------------------------
    int g = lane >> 2, tig = lane & 3;
    int orow0 = mtile * HTM + wm + g;
    int ocol0 = ntile * HTN + wn + tig * 2;
    float cs[4][2];
    if (CSUM) {
        #pragma unroll
        for (int fn = 0; fn < 4; fn++) { cs[fn][0] = 0.f; cs[fn][1] = 0.f; }
    }
    #pragma unroll
    for (int fn = 0; fn < 4; fn++) {
        int c = ocol0 + fn * 8;
        float b0 = bias[c], b1 = bias[c + 1];
        #pragma unroll
        for (int fm = 0; fm < 4; fm++) {
            int r = orow0 + fm * 16;
            size_t i0 = (size_t)r * ldc + c;
            size_t i1 = (size_t)(r + 8) * ldc + c;
            float v00 = acc[fm][fn][0] + b0, v01 = acc[fm][fn][1] + b1;
            float v10 = acc[fm][fn][2] + b0, v11 = acc[fm][fn][3] + b1;
            if (rowscale) {
                float r0 = rowscale[r], r1 = rowscale[r + 8];
                v00 *= r0; v01 *= r0; v10 *= r1; v11 *= r1;
            }
            if (add0) {
                float2 a0 = *(const float2*)(add0 + i0);
                float2 a1 = *(const float2*)(add0 + i1);
                v00 += a0.x; v01 += a0.y; v10 += a1.x; v11 += a1.y;
            }
            if (add1) {
                float2 a0 = *(const float2*)(add1 + i0);
                float2 a1 = *(const float2*)(add1 + i1);
                v00 += a0.x; v01 += a0.y; v10 += a1.x; v11 += a1.y;
            }
            if (CSUM) {
                cs[fn][0] += v00 + v10;
                cs[fn][1] += v01 + v11;
            }
            *(float2*)(C + i0) = make_float2(v00, v01);
            *(float2*)(C + i1) = make_float2(v10, v11);
        }
    }
    if (CSUM) {
        // reduce over g lanes (lane = g*4 + tig)
        #pragma unroll
        for (int fn = 0; fn < 4; fn++)
            #pragma unroll
            for (int j = 0; j < 2; j++)
                #pragma unroll
                for (int o = 16; o >= 4; o >>= 1)
                    cs[fn][j] += __shfl_xor_sync(~0u, cs[fn][j], o);
        int wmIdx = wid >> 2;
        if (g == 0) {
            #pragma unroll
            for (int fn = 0; fn < 4; fn++) {
                s_cs[wmIdx][wn + fn * 8 + tig * 2]     = cs[fn][0];
                s_cs[wmIdx][wn + fn * 8 + tig * 2 + 1] = cs[fn][1];
            }
        }
        __syncthreads();
        if (tid < 128)
            g_csum[(size_t)mtile * DD + ntile * 128 + tid] =
                s_cs[0][tid] + s_cs[1][tid];
    }
}

// ---------------- launch ----------------------------------------------------
extern "C" void kernel_launch(void* const* d_in, const int* in_sizes, int n_in,
                              void* d_out, int out_size) {
    const int*   tokens        = (const int*)  d_in[0];
    const float* embed         = (const float*)d_in[1];
    const float* ln_scale      = (const float*)d_in[2];
    const float* ln_bias       = (const float*)d_in[3];
    const float* phase_W       = (const float*)d_in[4];
    const float* phase_b       = (const float*)d_in[5];
    const float* amp_W         = (const float*)d_in[6];
    const float* amp_b         = (const float*)d_in[7];
    const float* value_W       = (const float*)d_in[8];
    const float* value_b       = (const float*)d_in[9];
    const float* out_ln_scale  = (const float*)d_in[10];
    const float* out_ln_bias   = (const float*)d_in[11];
    const float* out_W         = (const float*)d_in[12];
    const float* out_b         = (const float*)d_in[13];
    const float* normout_scale = (const float*)d_in[14];
    const float* normout_bias  = (const float*)d_in[15];
    const float* head_W        = (const float*)d_in[16];
    const float* head_b        = (const float*)d_in[17];
    float* out = (float*)d_out;

    float *h, *hn, *val, *sn, *coef;
    unsigned char *whi, *ahi, *alo, *lwhi;
    cudaGetSymbolAddress((void**)&h,    g_h);
    cudaGetSymbolAddress((void**)&hn,   g_hn);
    cudaGetSymbolAddress((void**)&val,  g_val);
    cudaGetSymbolAddress((void**)&sn,   g_sn);
    cudaGetSymbolAddress((void**)&coef, g_coef);
    cudaGetSymbolAddress((void**)&whi,  g_Whi);
    cudaGetSymbolAddress((void**)&ahi,  g_Ahi);
    cudaGetSymbolAddress((void**)&alo,  g_Alo);
    cudaGetSymbolAddress((void**)&lwhi, g_LWhi);

    cudaFuncSetAttribute(k_mm<true,  true >, cudaFuncAttributeMaxDynamicSharedMemorySize, SMEM_DYN);
    cudaFuncSetAttribute(k_mm<true,  false>, cudaFuncAttributeMaxDynamicSharedMemorySize, SMEM_DYN);
    cudaFuncSetAttribute(k_mm<false, false>, cudaFuncAttributeMaxDynamicSharedMemorySize, SMEM_DYN);

    k_embed<<<TOK, 128>>>(tokens, embed);
    k_convB<<<dim3(HNT, NKC), 256>>>(head_W, VV, whi);
    size_t lwstep = (size_t)DD * DD * 2;
    for (int i = 0; i < NLAYER; i++) {
        k_convB<<<dim3(LNT, NKC), 256>>>(value_W + (size_t)i * DD * DD, DD,
                                         lwhi + (2*i+0)*lwstep);
        k_convB<<<dim3(LNT, NKC), 256>>>(out_W + (size_t)i * DD * DD, DD,
                                         lwhi + (2*i+1)*lwstep);
    }

    dim3 scanGrid(DD / 128, NCH, BB);
    dim3 mmLayer(HMT, LNT);

    for (int i = 0; i < NLAYER; i++) {
        k_ln<<<TOK, 256>>>(h, ln_scale + i * DD, ln_bias + i * DD, hn, ahi, alo);
        k_coef<<<TOK / 64, 256>>>(hn, phase_W + (size_t)i * DD * PP, phase_b + i * PP,
                                  amp_W + (size_t)i * DD * PP, amp_b + i * PP);
        // val = (hn @ vW + vb) * coef, chunk sums fused
        k_mm<true, true><<<mmLayer, 256, SMEM_DYN>>>(
            ahi, alo, lwhi + (2*i+0)*lwstep,
            value_b + i * DD, coef, nullptr, nullptr, val, DD);
        k_scan<<<scanGrid, 128>>>();
        k_ln<<<TOK, 256>>>(val, out_ln_scale + i * DD, out_ln_bias + i * DD, sn, ahi, alo);
        // h = h + hn + sn @ oW + ob
        k_mm<true, false><<<mmLayer, 256, SMEM_DYN>>>(
            ahi, alo, lwhi + (2*i+1)*lwstep,
            out_b + i * DD, nullptr, h, hn, h, DD);
    }

    k_ln<<<TOK, 256>>>(h, normout_scale, normout_bias, hn, ahi, alo);
    // head: single-term fp16
    k_mm<false, false><<<dim3(HMT, HNT), 256, SMEM_DYN>>>(
        ahi, nullptr, whi, head_b, nullptr, nullptr, nullptr, out, VV);
}